// round 13
// baseline (speedup 1.0000x reference)
#include <cuda_runtime.h>
#include <cuda_fp8.h>
#include <cuda_fp16.h>
#include <cstdint>
#include <math.h>

#define Bb 2
#define Tt 1024
#define Cdim 2048
#define Hh 16
#define HDim 128
#define MLPD 8192
#define Mrows (Bb * Tt)

__device__ float g_xdq[Mrows * Cdim];
__device__ float g_hdq[Mrows * MLPD];
__device__ float g_q[Mrows * Cdim];
__device__ float g_k[Mrows * Cdim];
__device__ float g_v[Mrows * Cdim];
__device__ float g_scores[(size_t)Bb * Hh * Tt * Tt];
__device__ float g_ctx[Mrows * Cdim];
__device__ float g_tmp[Mrows * Cdim];
__device__ float g_x1[Mrows * Cdim];
__device__ float g_h[Mrows * MLPD];
__device__ float g_ffn[Mrows * Cdim];

// ---------------------------------------------------------------------------
// Packed f32x2 helpers (B300 dual-lane fp32 FMA). Lane-wise IEEE fp32 fma ->
// bit-identical to scalar fmaf sequences.
// ---------------------------------------------------------------------------
typedef unsigned long long u64t;
__device__ __forceinline__ u64t pk2(float lo, float hi) {
    u64t d;
    asm("mov.b64 %0, {%1,%2};" : "=l"(d) : "f"(lo), "f"(hi));
    return d;
}
__device__ __forceinline__ void upk2(float& lo, float& hi, u64t d) {
    asm("mov.b64 {%0,%1}, %2;" : "=f"(lo), "=f"(hi) : "l"(d));
}
__device__ __forceinline__ void fma2(u64t& c, u64t a, u64t b) {
    asm("fma.rn.f32x2 %0, %1, %2, %0;" : "+l"(c) : "l"(a), "l"(b));
}

// ---------------------------------------------------------------------------
// fp32 quantize-dequantize (bit-identical to R1/R9)
// ---------------------------------------------------------------------------
__global__ void qdq_kernel(const float* __restrict__ in, float* __restrict__ out,
                           float fmax, int e4m3)
{
    int blk  = blockIdx.x * 8 + (threadIdx.x >> 5);
    int lane = threadIdx.x & 31;
    size_t base = (size_t)blk * 128 + (size_t)lane * 4;
    float4 v = *reinterpret_cast<const float4*>(in + base);
    float am = fmaxf(fmaxf(fabsf(v.x), fabsf(v.y)), fmaxf(fabsf(v.z), fabsf(v.w)));
    #pragma unroll
    for (int o = 16; o > 0; o >>= 1)
        am = fmaxf(am, __shfl_xor_sync(0xffffffffu, am, o));
    float s = fmaxf(am / fmax, 1e-12f);
    float r4[4]; float xin[4] = {v.x, v.y, v.z, v.w};
    #pragma unroll
    for (int i = 0; i < 4; i++) {
        float r = xin[i] / s;
        __nv_fp8_storage_t f8 = __nv_cvt_float_to_fp8(r, __NV_SATFINITE, e4m3 ? __NV_E4M3 : __NV_E5M2);
        __half_raw hr = __nv_cvt_fp8_to_halfraw(f8, e4m3 ? __NV_E4M3 : __NV_E5M2);
        r4[i] = __half2float(*reinterpret_cast<__half*>(&hr)) * s;
    }
    float4 o4 = {r4[0], r4[1], r4[2], r4[3]};
    *reinterpret_cast<float4*>(out + base) = o4;
}

// ---------------------------------------------------------------------------
// Double-buffered fp32 SGEMM NT, BK=16, f32x2 inner loop.
// kk iterates k-values in the same order as BK=8 (two tiles concatenated)
// -> bit-identical accumulation. causal: skip tiles with n0 > m0+127.
// ---------------------------------------------------------------------------
__global__ void __launch_bounds__(256, 2)
gemm_nt(const float* __restrict__ A, const float* __restrict__ W, float* __restrict__ C,
        int K, int lda, int ldb, int ldc,
        int zdiv, long long sA1, long long sA2, long long sB1, long long sB2,
        long long sC1, long long sC2,
        const float* __restrict__ wscale, const float* __restrict__ bias,
        int act, int causal)
{
    __shared__ float As[2][16][132];
    __shared__ float Bs[2][16][132];
    int z = blockIdx.z;
    int z1 = z / zdiv, z2 = z % zdiv;
    A += z1 * sA1 + z2 * sA2;
    W += z1 * sB1 + z2 * sB2;
    C += z1 * sC1 + z2 * sC2;

    int m0 = blockIdx.y * 128, n0 = blockIdx.x * 128;
    if (causal && n0 > m0 + 127) return;

    int tid = threadIdx.x;
    int tx = tid & 15, ty = tid >> 4;
    int lrow = tid >> 1, lcol = (tid & 1) * 8;   // each thread: 8 consecutive k
    const float* gA = A + (size_t)(m0 + lrow) * lda + lcol;
    const float* gB = W + (size_t)(n0 + lrow) * ldb + lcol;

    u64t acc2[8][4];
    #pragma unroll
    for (int i = 0; i < 8; i++)
        #pragma unroll
        for (int j = 0; j < 4; j++) acc2[i][j] = 0ull;

    float4 av0 = *reinterpret_cast<const float4*>(gA);
    float4 av1 = *reinterpret_cast<const float4*>(gA + 4);
    float4 bv0 = *reinterpret_cast<const float4*>(gB);
    float4 bv1 = *reinterpret_cast<const float4*>(gB + 4);
    {
        float a8[8] = {av0.x, av0.y, av0.z, av0.w, av1.x, av1.y, av1.z, av1.w};
        float b8[8] = {bv0.x, bv0.y, bv0.z, bv0.w, bv1.x, bv1.y, bv1.z, bv1.w};
        #pragma unroll
        for (int i = 0; i < 8; i++) { As[0][lcol + i][lrow] = a8[i]; Bs[0][lcol + i][lrow] = b8[i]; }
    }
    __syncthreads();

    int nkt = K >> 4;
    for (int kt = 0; kt < nkt; kt++) {
        int cur = kt & 1;
        bool pf = (kt + 1) < nkt;
        if (pf) {
            const float* pA = gA + (kt + 1) * 16;
            const float* pB = gB + (kt + 1) * 16;
            av0 = *reinterpret_cast<const float4*>(pA);
            av1 = *reinterpret_cast<const float4*>(pA + 4);
            bv0 = *reinterpret_cast<const float4*>(pB);
            bv1 = *reinterpret_cast<const float4*>(pB + 4);
        }
        #pragma unroll
        for (int kk = 0; kk < 16; kk++) {
            float4 a0 = *reinterpret_cast<const float4*>(&As[cur][kk][ty * 8]);
            float4 a1 = *reinterpret_cast<const float4*>(&As[cur][kk][ty * 8 + 4]);
            float4 b0 = *reinterpret_cast<const float4*>(&Bs[cur][kk][tx * 8]);
            float4 b1 = *reinterpret_cast<const float4*>(&Bs[cur][kk][tx * 8 + 4]);
            float a[8] = {a0.x, a0.y, a0.z, a0.w, a1.x, a1.y, a1.z, a1.w};
            u64t ad[8], bd[4];
            #pragma unroll
            for (int i = 0; i < 8; i++) ad[i] = pk2(a[i], a[i]);
            bd[0] = pk2(b0.x, b0.y); bd[1] = pk2(b0.z, b0.w);
            bd[2] = pk2(b1.x, b1.y); bd[3] = pk2(b1.z, b1.w);
            #pragma unroll
            for (int i = 0; i < 8; i++)
                #pragma unroll
                for (int j = 0; j < 4; j++) fma2(acc2[i][j], ad[i], bd[j]);
        }
        if (pf) {
            int nb = cur ^ 1;
            float a8[8] = {av0.x, av0.y, av0.z, av0.w, av1.x, av1.y, av1.z, av1.w};
            float b8[8] = {bv0.x, bv0.y, bv0.z, bv0.w, bv1.x, bv1.y, bv1.z, bv1.w};
            #pragma unroll
            for (int i = 0; i < 8; i++) { As[nb][lcol + i][lrow] = a8[i]; Bs[nb][lcol + i][lrow] = b8[i]; }
        }
        __syncthreads();
    }

    #pragma unroll
    for (int i = 0; i < 8; i++) {
        int m = m0 + ty * 8 + i;
        #pragma unroll
        for (int j = 0; j < 4; j++) {
            float vlo, vhi;
            upk2(vlo, vhi, acc2[i][j]);
            int n = n0 + tx * 8 + j * 2;
            float ws0 = wscale ? wscale[n >> 7] : 1.0f;
            float ws1 = wscale ? wscale[(n + 1) >> 7] : 1.0f;
            vlo *= ws0; vhi *= ws1;
            if (bias) { vlo += bias[n]; vhi += bias[n + 1]; }
            if (act) {
                vlo = 0.5f * vlo * (1.0f + erff(vlo * 0.7071067811865476f));
                vhi = 0.5f * vhi * (1.0f + erff(vhi * 0.7071067811865476f));
            }
            C[(size_t)m * ldc + n]     = vlo;
            C[(size_t)m * ldc + n + 1] = vhi;
        }
    }
}

// ---------------------------------------------------------------------------
// Double-buffered fp32 SGEMM NN (attn @ V), BK=16, f32x2. Causal K cap.
// ---------------------------------------------------------------------------
__global__ void __launch_bounds__(256, 2)
gemm_nn(const float* __restrict__ A, const float* __restrict__ Bm, float* __restrict__ C,
        int K, int lda, int ldb, int ldc,
        int zdiv, long long sA1, long long sA2, long long sB1, long long sB2,
        long long sC1, long long sC2, int causal)
{
    __shared__ float As[2][16][132];
    __shared__ float Bs[2][16][132];
    int z = blockIdx.z;
    int z1 = z / zdiv, z2 = z % zdiv;
    A  += z1 * sA1 + z2 * sA2;
    Bm += z1 * sB1 + z2 * sB2;
    C  += z1 * sC1 + z2 * sC2;
    int tid = threadIdx.x;
    int tx = tid & 15, ty = tid >> 4;
    int m0 = blockIdx.y * 128, n0 = blockIdx.x * 128;
    int arow = tid >> 1, acol = (tid & 1) * 8;
    int brow = tid >> 4, bcol = (tid & 15) * 8;   // 16 k-rows x 128 n-cols
    const float* gA = A + (size_t)(m0 + arow) * lda + acol;
    const float* gB = Bm + (size_t)brow * ldb + n0 + bcol;

    int Keff = causal ? (m0 + 128 < K ? m0 + 128 : K) : K;

    u64t acc2[8][4];
    #pragma unroll
    for (int i = 0; i < 8; i++)
        #pragma unroll
        for (int j = 0; j < 4; j++) acc2[i][j] = 0ull;

    float4 av0 = *reinterpret_cast<const float4*>(gA);
    float4 av1 = *reinterpret_cast<const float4*>(gA + 4);
    float4 bv0 = *reinterpret_cast<const float4*>(gB);
    float4 bv1 = *reinterpret_cast<const float4*>(gB + 4);
    {
        float a8[8] = {av0.x, av0.y, av0.z, av0.w, av1.x, av1.y, av1.z, av1.w};
        #pragma unroll
        for (int i = 0; i < 8; i++) As[0][acol + i][arow] = a8[i];
        *reinterpret_cast<float4*>(&Bs[0][brow][bcol])     = bv0;
        *reinterpret_cast<float4*>(&Bs[0][brow][bcol + 4]) = bv1;
    }
    __syncthreads();

    int nkt = Keff >> 4;
    for (int kt = 0; kt < nkt; kt++) {
        int cur = kt & 1;
        bool pf = (kt + 1) < nkt;
        if (pf) {
            const float* pA = gA + (kt + 1) * 16;
            const float* pB = gB + (size_t)(kt + 1) * 16 * ldb;
            av0 = *reinterpret_cast<const float4*>(pA);
            av1 = *reinterpret_cast<const float4*>(pA + 4);
            bv0 = *reinterpret_cast<const float4*>(pB);
            bv1 = *reinterpret_cast<const float4*>(pB + 4);
        }
        #pragma unroll
        for (int kk = 0; kk < 16; kk++) {
            float4 a0 = *reinterpret_cast<const float4*>(&As[cur][kk][ty * 8]);
            float4 a1 = *reinterpret_cast<const float4*>(&As[cur][kk][ty * 8 + 4]);
            float4 b0 = *reinterpret_cast<const float4*>(&Bs[cur][kk][tx * 8]);
            float4 b1 = *reinterpret_cast<const float4*>(&Bs[cur][kk][tx * 8 + 4]);
            float a[8] = {a0.x, a0.y, a0.z, a0.w, a1.x, a1.y, a1.z, a1.w};
            u64t ad[8], bd[4];
            #pragma unroll
            for (int i = 0; i < 8; i++) ad[i] = pk2(a[i], a[i]);
            bd[0] = pk2(b0.x, b0.y); bd[1] = pk2(b0.z, b0.w);
            bd[2] = pk2(b1.x, b1.y); bd[3] = pk2(b1.z, b1.w);
            #pragma unroll
            for (int i = 0; i < 8; i++)
                #pragma unroll
                for (int j = 0; j < 4; j++) fma2(acc2[i][j], ad[i], bd[j]);
        }
        if (pf) {
            int nb = cur ^ 1;
            float a8[8] = {av0.x, av0.y, av0.z, av0.w, av1.x, av1.y, av1.z, av1.w};
            #pragma unroll
            for (int i = 0; i < 8; i++) As[nb][acol + i][arow] = a8[i];
            *reinterpret_cast<float4*>(&Bs[nb][brow][bcol])     = bv0;
            *reinterpret_cast<float4*>(&Bs[nb][brow][bcol + 4]) = bv1;
        }
        __syncthreads();
    }

    #pragma unroll
    for (int i = 0; i < 8; i++) {
        int m = m0 + ty * 8 + i;
        #pragma unroll
        for (int j = 0; j < 4; j++) {
            float vlo, vhi;
            upk2(vlo, vhi, acc2[i][j]);
            int n = n0 + tx * 8 + j * 2;
            C[(size_t)m * ldc + n]     = vlo;
            C[(size_t)m * ldc + n + 1] = vhi;
        }
    }
}

// ---------------------------------------------------------------------------
// Causal-masked softmax — verbatim R1/R9
// ---------------------------------------------------------------------------
__global__ void softmax_kernel(float* __restrict__ S, const int* __restrict__ mask, float scale)
{
    int row = blockIdx.x;
    int q = row % Tt;
    int b = row / (Hh * Tt);
    float* sr = S + (size_t)row * Tt;
    const int* mr = mask + ((size_t)b * Tt + q) * Tt;
    int tid = threadIdx.x;
    __shared__ float red[256];
    float vals[4];
    float lmax = -INFINITY;
    #pragma unroll
    for (int it = 0; it < 4; it++) {
        int i = tid + it * 256;
        float v = mr[i] ? sr[i] * scale : -INFINITY;
        vals[it] = v;
        lmax = fmaxf(lmax, v);
    }
    red[tid] = lmax; __syncthreads();
    for (int o = 128; o > 0; o >>= 1) {
        if (tid < o) red[tid] = fmaxf(red[tid], red[tid + o]);
        __syncthreads();
    }
    float mx = red[0];
    __syncthreads();
    float lsum = 0.0f;
    #pragma unroll
    for (int it = 0; it < 4; it++) {
        float e = expf(vals[it] - mx);
        vals[it] = e;
        lsum += e;
    }
    red[tid] = lsum; __syncthreads();
    for (int o = 128; o > 0; o >>= 1) {
        if (tid < o) red[tid] += red[tid + o];
        __syncthreads();
    }
    float inv = 1.0f / red[0];
    #pragma unroll
    for (int it = 0; it < 4; it++) {
        int i = tid + it * 256;
        sr[i] = vals[it] * inv;
    }
}

// ---------------------------------------------------------------------------
// LayerNorm(x + y) — verbatim R1/R9
// ---------------------------------------------------------------------------
__global__ void addln_kernel(const float* __restrict__ x, const float* __restrict__ y,
                             float* __restrict__ out,
                             const float* __restrict__ g, const float* __restrict__ gs,
                             const float* __restrict__ b, const float* __restrict__ bs)
{
    int row = blockIdx.x;
    const float* xr = x + (size_t)row * Cdim;
    const float* yr = y + (size_t)row * Cdim;
    float* outr = out + (size_t)row * Cdim;
    __shared__ float buf[Cdim];
    __shared__ float red[256];
    int tid = threadIdx.x;
    float lsum = 0.0f;
    #pragma unroll
    for (int it = 0; it < Cdim / 256; it++) {
        int i = tid + it * 256;
        float v = xr[i] + yr[i];
        buf[i] = v;
        lsum += v;
    }
    red[tid] = lsum; __syncthreads();
    for (int o = 128; o > 0; o >>= 1) {
        if (tid < o) red[tid] += red[tid + o];
        __syncthreads();
    }
    float mean = red[0] * (1.0f / Cdim);
    __syncthreads();
    float lvar = 0.0f;
    #pragma unroll
    for (int it = 0; it < Cdim / 256; it++) {
        int i = tid + it * 256;
        float d = buf[i] - mean;
        lvar += d * d;
    }
    red[tid] = lvar; __syncthreads();
    for (int o = 128; o > 0; o >>= 1) {
        if (tid < o) red[tid] += red[tid + o];
        __syncthreads();
    }
    float rstd = rsqrtf(red[0] * (1.0f / Cdim) + 1e-5f);
    #pragma unroll
    for (int it = 0; it < Cdim / 256; it++) {
        int i = tid + it * 256;
        float d = (buf[i] - mean) * rstd;
        outr[i] = d * (g[i] * gs[i >> 7]) + b[i] * bs[i >> 7];
    }
}

// ---------------------------------------------------------------------------
// Launch pipeline
// ---------------------------------------------------------------------------
extern "C" void kernel_launch(void* const* d_in, const int* in_sizes, int n_in,
                              void* d_out, int out_size)
{
    const float* x     = (const float*)d_in[0];
    const int*   mask  = (const int*)  d_in[1];
    const float* wq    = (const float*)d_in[2];
    const float* qs    = (const float*)d_in[3];
    const float* wk    = (const float*)d_in[4];
    const float* ks    = (const float*)d_in[5];
    const float* wv    = (const float*)d_in[6];
    const float* vs    = (const float*)d_in[7];
    const float* wo    = (const float*)d_in[8];
    const float* os_   = (const float*)d_in[9];
    const float* fc1w  = (const float*)d_in[10];
    const float* fc1s  = (const float*)d_in[11];
    const float* fc1b  = (const float*)d_in[12];
    const float* fc2w  = (const float*)d_in[13];
    const float* fc2s  = (const float*)d_in[14];
    const float* fc2b  = (const float*)d_in[15];
    const float* l1g   = (const float*)d_in[16];
    const float* l1gs  = (const float*)d_in[17];
    const float* l1b   = (const float*)d_in[18];
    const float* l1bs  = (const float*)d_in[19];
    const float* l2g   = (const float*)d_in[20];
    const float* l2gs  = (const float*)d_in[21];
    const float* l2b   = (const float*)d_in[22];
    const float* l2bs  = (const float*)d_in[23];
    float* out = (float*)d_out;

    void* p;
    cudaGetSymbolAddress(&p, g_xdq);    float* xdq = (float*)p;
    cudaGetSymbolAddress(&p, g_hdq);    float* hdq = (float*)p;
    cudaGetSymbolAddress(&p, g_q);      float* qb  = (float*)p;
    cudaGetSymbolAddress(&p, g_k);      float* kb  = (float*)p;
    cudaGetSymbolAddress(&p, g_v);      float* vb  = (float*)p;
    cudaGetSymbolAddress(&p, g_scores); float* sc  = (float*)p;
    cudaGetSymbolAddress(&p, g_ctx);    float* ctx = (float*)p;
    cudaGetSymbolAddress(&p, g_tmp);    float* tmp = (float*)p;
    cudaGetSymbolAddress(&p, g_x1);     float* x1  = (float*)p;
    cudaGetSymbolAddress(&p, g_h);      float* hb  = (float*)p;
    cudaGetSymbolAddress(&p, g_ffn);    float* ffn = (float*)p;

    const float E5MAX = 57344.0f, E4MAX = 448.0f;
    const float INV_SQRT_HD = 0.08838834764831845f;

    // 1. qdq x (E5M2)
    qdq_kernel<<<(Mrows * Cdim / 128) / 8, 256>>>(x, xdq, E5MAX, 0);

    // 2. QKV projections
    dim3 gl(Cdim / 128, Mrows / 128, 1);
    gemm_nt<<<gl, 256>>>(xdq, wq, qb, Cdim, Cdim, Cdim, Cdim,
                         1, 0, 0, 0, 0, 0, 0, qs, nullptr, 0, 0);
    gemm_nt<<<gl, 256>>>(xdq, wk, kb, Cdim, Cdim, Cdim, Cdim,
                         1, 0, 0, 0, 0, 0, 0, ks, nullptr, 0, 0);
    gemm_nt<<<gl, 256>>>(xdq, wv, vb, Cdim, Cdim, Cdim, Cdim,
                         1, 0, 0, 0, 0, 0, 0, vs, nullptr, 0, 0);

    // 3. scores = Q @ K^T (causal tiles only)
    dim3 gsc(Tt / 128, Tt / 128, Bb * Hh);
    gemm_nt<<<gsc, 256>>>(qb, kb, sc, HDim, Cdim, Cdim, Tt,
                          Hh, (long long)Tt * Cdim, 128, (long long)Tt * Cdim, 128,
                          (long long)Hh * Tt * Tt, (long long)Tt * Tt,
                          nullptr, nullptr, 0, 1);

    // 4. masked softmax
    softmax_kernel<<<Bb * Hh * Tt, 256>>>(sc, mask, INV_SQRT_HD);

    // 5. ctx = attn @ V (K capped causally)
    dim3 gcx(1, Tt / 128, Bb * Hh);
    gemm_nn<<<gcx, 256>>>(sc, vb, ctx, Tt, Tt, Cdim, Cdim,
                          Hh, (long long)Hh * Tt * Tt, (long long)Tt * Tt,
                          (long long)Tt * Cdim, 128, (long long)Tt * Cdim, 128, 1);

    // 6. out projection
    qdq_kernel<<<(Mrows * Cdim / 128) / 8, 256>>>(ctx, xdq, E5MAX, 0);
    gemm_nt<<<gl, 256>>>(xdq, wo, tmp, Cdim, Cdim, Cdim, Cdim,
                         1, 0, 0, 0, 0, 0, 0, os_, nullptr, 0, 0);

    // 7. x1 = LN1(x + attn_out)
    addln_kernel<<<Mrows, 256>>>(x, tmp, x1, l1g, l1gs, l1b, l1bs);

    // 8. fc1 + bias + exact GELU
    qdq_kernel<<<(Mrows * Cdim / 128) / 8, 256>>>(x1, xdq, E4MAX, 1);
    dim3 gf1(MLPD / 128, Mrows / 128, 1);
    gemm_nt<<<gf1, 256>>>(xdq, fc1w, hb, Cdim, Cdim, Cdim, MLPD,
                          1, 0, 0, 0, 0, 0, 0, fc1s, fc1b, 1, 0);

    // 9. fc2 + bias
    qdq_kernel<<<(Mrows * MLPD / 128) / 8, 256>>>(hb, hdq, E4MAX, 1);
    dim3 gf2(Cdim / 128, Mrows / 128, 1);
    gemm_nt<<<gf2, 256>>>(hdq, fc2w, ffn, MLPD, MLPD, MLPD, Cdim,
                          1, 0, 0, 0, 0, 0, 0, fc2s, fc2b, 0, 0);

    // 10. out = LN2(x1 + ffn)
    addln_kernel<<<Mrows, 256>>>(x1, ffn, out, l2g, l2gs, l2b, l2bs);
}

// round 14
// speedup vs baseline: 1.0864x; 1.0864x over previous
#include <cuda_runtime.h>
#include <cuda_fp8.h>
#include <cuda_fp16.h>
#include <cstdint>
#include <math.h>

#define Bb 2
#define Tt 1024
#define Cdim 2048
#define Hh 16
#define HDim 128
#define MLPD 8192
#define Mrows (Bb * Tt)

__device__ float g_xdq[Mrows * Cdim];
__device__ float g_hdq[Mrows * MLPD];
__device__ float g_q[Mrows * Cdim];
__device__ float g_k[Mrows * Cdim];
__device__ float g_v[Mrows * Cdim];
__device__ float g_scores[(size_t)Bb * Hh * Tt * Tt];
__device__ float g_ctx[Mrows * Cdim];
__device__ float g_tmp[Mrows * Cdim];
__device__ float g_x1[Mrows * Cdim];
__device__ float g_h[Mrows * MLPD];
__device__ float g_ffn[Mrows * Cdim];

// ---------------------------------------------------------------------------
// Packed f32x2 helpers (B300 dual-lane fp32 FMA). Lane-wise IEEE fp32 fma ->
// bit-identical to scalar fmaf sequences.
// ---------------------------------------------------------------------------
typedef unsigned long long u64t;
__device__ __forceinline__ u64t pk2(float lo, float hi) {
    u64t d;
    asm("mov.b64 %0, {%1,%2};" : "=l"(d) : "f"(lo), "f"(hi));
    return d;
}
__device__ __forceinline__ void upk2(float& lo, float& hi, u64t d) {
    asm("mov.b64 {%0,%1}, %2;" : "=f"(lo), "=f"(hi) : "l"(d));
}
__device__ __forceinline__ void fma2(u64t& c, u64t a, u64t b) {
    asm("fma.rn.f32x2 %0, %1, %2, %0;" : "+l"(c) : "l"(a), "l"(b));
}

// ---------------------------------------------------------------------------
// fp32 quantize-dequantize (bit-identical to R1/R9)
// ---------------------------------------------------------------------------
__global__ void qdq_kernel(const float* __restrict__ in, float* __restrict__ out,
                           float fmax, int e4m3)
{
    int blk  = blockIdx.x * 8 + (threadIdx.x >> 5);
    int lane = threadIdx.x & 31;
    size_t base = (size_t)blk * 128 + (size_t)lane * 4;
    float4 v = *reinterpret_cast<const float4*>(in + base);
    float am = fmaxf(fmaxf(fabsf(v.x), fabsf(v.y)), fmaxf(fabsf(v.z), fabsf(v.w)));
    #pragma unroll
    for (int o = 16; o > 0; o >>= 1)
        am = fmaxf(am, __shfl_xor_sync(0xffffffffu, am, o));
    float s = fmaxf(am / fmax, 1e-12f);
    float r4[4]; float xin[4] = {v.x, v.y, v.z, v.w};
    #pragma unroll
    for (int i = 0; i < 4; i++) {
        float r = xin[i] / s;
        __nv_fp8_storage_t f8 = __nv_cvt_float_to_fp8(r, __NV_SATFINITE, e4m3 ? __NV_E4M3 : __NV_E5M2);
        __half_raw hr = __nv_cvt_fp8_to_halfraw(f8, e4m3 ? __NV_E4M3 : __NV_E5M2);
        r4[i] = __half2float(*reinterpret_cast<__half*>(&hr)) * s;
    }
    float4 o4 = {r4[0], r4[1], r4[2], r4[3]};
    *reinterpret_cast<float4*>(out + base) = o4;
}

// ---------------------------------------------------------------------------
// Double-buffered fp32 SGEMM NT: 128 threads, 16x8 per thread, BK=8, f32x2.
// LDS per FMA2 cut to 1.5 B (was 2.0). Per-element k-order unchanged ->
// bit-identical results. causal: skip tiles with n0 > m0+127.
// ---------------------------------------------------------------------------
__global__ void __launch_bounds__(128, 2)
gemm_nt(const float* __restrict__ A, const float* __restrict__ W, float* __restrict__ C,
        int K, int lda, int ldb, int ldc,
        int zdiv, long long sA1, long long sA2, long long sB1, long long sB2,
        long long sC1, long long sC2,
        const float* __restrict__ wscale, const float* __restrict__ bias,
        int act, int causal)
{
    __shared__ float As[2][8][132];
    __shared__ float Bs[2][8][132];
    int z = blockIdx.z;
    int z1 = z / zdiv, z2 = z % zdiv;
    A += z1 * sA1 + z2 * sA2;
    W += z1 * sB1 + z2 * sB2;
    C += z1 * sC1 + z2 * sC2;

    int m0 = blockIdx.y * 128, n0 = blockIdx.x * 128;
    if (causal && n0 > m0 + 127) return;

    int tid = threadIdx.x;
    int tx = tid & 15, ty = tid >> 4;          // ty: 0..7 (16 m-rows each)
    const float* gA = A + (size_t)(m0 + tid) * lda;   // loader: one row per thread
    const float* gB = W + (size_t)(n0 + tid) * ldb;

    u64t acc2[16][4];
    #pragma unroll
    for (int i = 0; i < 16; i++)
        #pragma unroll
        for (int j = 0; j < 4; j++) acc2[i][j] = 0ull;

    float4 av0 = *reinterpret_cast<const float4*>(gA);
    float4 av1 = *reinterpret_cast<const float4*>(gA + 4);
    float4 bv0 = *reinterpret_cast<const float4*>(gB);
    float4 bv1 = *reinterpret_cast<const float4*>(gB + 4);
    {
        float a8[8] = {av0.x, av0.y, av0.z, av0.w, av1.x, av1.y, av1.z, av1.w};
        float b8[8] = {bv0.x, bv0.y, bv0.z, bv0.w, bv1.x, bv1.y, bv1.z, bv1.w};
        #pragma unroll
        for (int q = 0; q < 8; q++) { As[0][q][tid] = a8[q]; Bs[0][q][tid] = b8[q]; }
    }
    __syncthreads();

    int nkt = K >> 3;
    for (int kt = 0; kt < nkt; kt++) {
        int cur = kt & 1;
        bool pf = (kt + 1) < nkt;
        if (pf) {
            const float* pA = gA + (kt + 1) * 8;
            const float* pB = gB + (kt + 1) * 8;
            av0 = *reinterpret_cast<const float4*>(pA);
            av1 = *reinterpret_cast<const float4*>(pA + 4);
            bv0 = *reinterpret_cast<const float4*>(pB);
            bv1 = *reinterpret_cast<const float4*>(pB + 4);
        }
        #pragma unroll
        for (int kk = 0; kk < 8; kk++) {
            float4 a0 = *reinterpret_cast<const float4*>(&As[cur][kk][ty * 16]);
            float4 a1 = *reinterpret_cast<const float4*>(&As[cur][kk][ty * 16 + 4]);
            float4 a2 = *reinterpret_cast<const float4*>(&As[cur][kk][ty * 16 + 8]);
            float4 a3 = *reinterpret_cast<const float4*>(&As[cur][kk][ty * 16 + 12]);
            float4 b0 = *reinterpret_cast<const float4*>(&Bs[cur][kk][tx * 8]);
            float4 b1 = *reinterpret_cast<const float4*>(&Bs[cur][kk][tx * 8 + 4]);
            float a[16] = {a0.x, a0.y, a0.z, a0.w, a1.x, a1.y, a1.z, a1.w,
                           a2.x, a2.y, a2.z, a2.w, a3.x, a3.y, a3.z, a3.w};
            u64t ad[16], bd[4];
            #pragma unroll
            for (int i = 0; i < 16; i++) ad[i] = pk2(a[i], a[i]);
            bd[0] = pk2(b0.x, b0.y); bd[1] = pk2(b0.z, b0.w);
            bd[2] = pk2(b1.x, b1.y); bd[3] = pk2(b1.z, b1.w);
            #pragma unroll
            for (int i = 0; i < 16; i++)
                #pragma unroll
                for (int j = 0; j < 4; j++) fma2(acc2[i][j], ad[i], bd[j]);
        }
        if (pf) {
            int nb = cur ^ 1;
            float a8[8] = {av0.x, av0.y, av0.z, av0.w, av1.x, av1.y, av1.z, av1.w};
            float b8[8] = {bv0.x, bv0.y, bv0.z, bv0.w, bv1.x, bv1.y, bv1.z, bv1.w};
            #pragma unroll
            for (int q = 0; q < 8; q++) { As[nb][q][tid] = a8[q]; Bs[nb][q][tid] = b8[q]; }
        }
        __syncthreads();
    }

    #pragma unroll
    for (int i = 0; i < 16; i++) {
        int m = m0 + ty * 16 + i;
        #pragma unroll
        for (int j = 0; j < 4; j++) {
            float vlo, vhi;
            upk2(vlo, vhi, acc2[i][j]);
            int n = n0 + tx * 8 + j * 2;
            float ws0 = wscale ? wscale[n >> 7] : 1.0f;
            float ws1 = wscale ? wscale[(n + 1) >> 7] : 1.0f;
            vlo *= ws0; vhi *= ws1;
            if (bias) { vlo += bias[n]; vhi += bias[n + 1]; }
            if (act) {
                vlo = 0.5f * vlo * (1.0f + erff(vlo * 0.7071067811865476f));
                vhi = 0.5f * vhi * (1.0f + erff(vhi * 0.7071067811865476f));
            }
            C[(size_t)m * ldc + n]     = vlo;
            C[(size_t)m * ldc + n + 1] = vhi;
        }
    }
}

// ---------------------------------------------------------------------------
// Double-buffered fp32 SGEMM NN (attn @ V), BK=8, f32x2 (proven R11 form).
// Exact causal K cap at m0+128.
// ---------------------------------------------------------------------------
__global__ void __launch_bounds__(256, 2)
gemm_nn(const float* __restrict__ A, const float* __restrict__ Bm, float* __restrict__ C,
        int K, int lda, int ldb, int ldc,
        int zdiv, long long sA1, long long sA2, long long sB1, long long sB2,
        long long sC1, long long sC2, int causal)
{
    __shared__ float As[2][8][132];
    __shared__ float Bs[2][8][132];
    int z = blockIdx.z;
    int z1 = z / zdiv, z2 = z % zdiv;
    A  += z1 * sA1 + z2 * sA2;
    Bm += z1 * sB1 + z2 * sB2;
    C  += z1 * sC1 + z2 * sC2;
    int tid = threadIdx.x;
    int tx = tid & 15, ty = tid >> 4;
    int m0 = blockIdx.y * 128, n0 = blockIdx.x * 128;
    int arow = tid >> 1, acol = (tid & 1) * 4;
    int brow = tid >> 5, bcol = (tid & 31) * 4;
    const float* gA = A + (size_t)(m0 + arow) * lda + acol;
    const float* gB = Bm + (size_t)brow * ldb + n0 + bcol;

    int Keff = causal ? (m0 + 128 < K ? m0 + 128 : K) : K;

    u64t acc2[8][4];
    #pragma unroll
    for (int i = 0; i < 8; i++)
        #pragma unroll
        for (int j = 0; j < 4; j++) acc2[i][j] = 0ull;

    float4 av = *reinterpret_cast<const float4*>(gA);
    float4 bv = *reinterpret_cast<const float4*>(gB);
    As[0][acol + 0][arow] = av.x; As[0][acol + 1][arow] = av.y;
    As[0][acol + 2][arow] = av.z; As[0][acol + 3][arow] = av.w;
    *reinterpret_cast<float4*>(&Bs[0][brow][bcol]) = bv;
    __syncthreads();

    int nkt = Keff >> 3;
    for (int kt = 0; kt < nkt; kt++) {
        int cur = kt & 1;
        bool pf = (kt + 1) < nkt;
        if (pf) {
            av = *reinterpret_cast<const float4*>(gA + (kt + 1) * 8);
            bv = *reinterpret_cast<const float4*>(gB + (size_t)(kt + 1) * 8 * ldb);
        }
        #pragma unroll
        for (int kk = 0; kk < 8; kk++) {
            float4 a0 = *reinterpret_cast<const float4*>(&As[cur][kk][ty * 8]);
            float4 a1 = *reinterpret_cast<const float4*>(&As[cur][kk][ty * 8 + 4]);
            float4 b0 = *reinterpret_cast<const float4*>(&Bs[cur][kk][tx * 8]);
            float4 b1 = *reinterpret_cast<const float4*>(&Bs[cur][kk][tx * 8 + 4]);
            float a[8] = {a0.x, a0.y, a0.z, a0.w, a1.x, a1.y, a1.z, a1.w};
            u64t ad[8], bd[4];
            #pragma unroll
            for (int i = 0; i < 8; i++) ad[i] = pk2(a[i], a[i]);
            bd[0] = pk2(b0.x, b0.y); bd[1] = pk2(b0.z, b0.w);
            bd[2] = pk2(b1.x, b1.y); bd[3] = pk2(b1.z, b1.w);
            #pragma unroll
            for (int i = 0; i < 8; i++)
                #pragma unroll
                for (int j = 0; j < 4; j++) fma2(acc2[i][j], ad[i], bd[j]);
        }
        if (pf) {
            int nb = cur ^ 1;
            As[nb][acol + 0][arow] = av.x; As[nb][acol + 1][arow] = av.y;
            As[nb][acol + 2][arow] = av.z; As[nb][acol + 3][arow] = av.w;
            *reinterpret_cast<float4*>(&Bs[nb][brow][bcol]) = bv;
        }
        __syncthreads();
    }

    #pragma unroll
    for (int i = 0; i < 8; i++) {
        int m = m0 + ty * 8 + i;
        #pragma unroll
        for (int j = 0; j < 4; j++) {
            float vlo, vhi;
            upk2(vlo, vhi, acc2[i][j]);
            int n = n0 + tx * 8 + j * 2;
            C[(size_t)m * ldc + n]     = vlo;
            C[(size_t)m * ldc + n + 1] = vhi;
        }
    }
}

// ---------------------------------------------------------------------------
// Causal-masked softmax — verbatim R1/R9
// ---------------------------------------------------------------------------
__global__ void softmax_kernel(float* __restrict__ S, const int* __restrict__ mask, float scale)
{
    int row = blockIdx.x;
    int q = row % Tt;
    int b = row / (Hh * Tt);
    float* sr = S + (size_t)row * Tt;
    const int* mr = mask + ((size_t)b * Tt + q) * Tt;
    int tid = threadIdx.x;
    __shared__ float red[256];
    float vals[4];
    float lmax = -INFINITY;
    #pragma unroll
    for (int it = 0; it < 4; it++) {
        int i = tid + it * 256;
        float v = mr[i] ? sr[i] * scale : -INFINITY;
        vals[it] = v;
        lmax = fmaxf(lmax, v);
    }
    red[tid] = lmax; __syncthreads();
    for (int o = 128; o > 0; o >>= 1) {
        if (tid < o) red[tid] = fmaxf(red[tid], red[tid + o]);
        __syncthreads();
    }
    float mx = red[0];
    __syncthreads();
    float lsum = 0.0f;
    #pragma unroll
    for (int it = 0; it < 4; it++) {
        float e = expf(vals[it] - mx);
        vals[it] = e;
        lsum += e;
    }
    red[tid] = lsum; __syncthreads();
    for (int o = 128; o > 0; o >>= 1) {
        if (tid < o) red[tid] += red[tid + o];
        __syncthreads();
    }
    float inv = 1.0f / red[0];
    #pragma unroll
    for (int it = 0; it < 4; it++) {
        int i = tid + it * 256;
        sr[i] = vals[it] * inv;
    }
}

// ---------------------------------------------------------------------------
// LayerNorm(x + y) — verbatim R1/R9
// ---------------------------------------------------------------------------
__global__ void addln_kernel(const float* __restrict__ x, const float* __restrict__ y,
                             float* __restrict__ out,
                             const float* __restrict__ g, const float* __restrict__ gs,
                             const float* __restrict__ b, const float* __restrict__ bs)
{
    int row = blockIdx.x;
    const float* xr = x + (size_t)row * Cdim;
    const float* yr = y + (size_t)row * Cdim;
    float* outr = out + (size_t)row * Cdim;
    __shared__ float buf[Cdim];
    __shared__ float red[256];
    int tid = threadIdx.x;
    float lsum = 0.0f;
    #pragma unroll
    for (int it = 0; it < Cdim / 256; it++) {
        int i = tid + it * 256;
        float v = xr[i] + yr[i];
        buf[i] = v;
        lsum += v;
    }
    red[tid] = lsum; __syncthreads();
    for (int o = 128; o > 0; o >>= 1) {
        if (tid < o) red[tid] += red[tid + o];
        __syncthreads();
    }
    float mean = red[0] * (1.0f / Cdim);
    __syncthreads();
    float lvar = 0.0f;
    #pragma unroll
    for (int it = 0; it < Cdim / 256; it++) {
        int i = tid + it * 256;
        float d = buf[i] - mean;
        lvar += d * d;
    }
    red[tid] = lvar; __syncthreads();
    for (int o = 128; o > 0; o >>= 1) {
        if (tid < o) red[tid] += red[tid + o];
        __syncthreads();
    }
    float rstd = rsqrtf(red[0] * (1.0f / Cdim) + 1e-5f);
    #pragma unroll
    for (int it = 0; it < Cdim / 256; it++) {
        int i = tid + it * 256;
        float d = (buf[i] - mean) * rstd;
        outr[i] = d * (g[i] * gs[i >> 7]) + b[i] * bs[i >> 7];
    }
}

// ---------------------------------------------------------------------------
// Launch pipeline
// ---------------------------------------------------------------------------
extern "C" void kernel_launch(void* const* d_in, const int* in_sizes, int n_in,
                              void* d_out, int out_size)
{
    const float* x     = (const float*)d_in[0];
    const int*   mask  = (const int*)  d_in[1];
    const float* wq    = (const float*)d_in[2];
    const float* qs    = (const float*)d_in[3];
    const float* wk    = (const float*)d_in[4];
    const float* ks    = (const float*)d_in[5];
    const float* wv    = (const float*)d_in[6];
    const float* vs    = (const float*)d_in[7];
    const float* wo    = (const float*)d_in[8];
    const float* os_   = (const float*)d_in[9];
    const float* fc1w  = (const float*)d_in[10];
    const float* fc1s  = (const float*)d_in[11];
    const float* fc1b  = (const float*)d_in[12];
    const float* fc2w  = (const float*)d_in[13];
    const float* fc2s  = (const float*)d_in[14];
    const float* fc2b  = (const float*)d_in[15];
    const float* l1g   = (const float*)d_in[16];
    const float* l1gs  = (const float*)d_in[17];
    const float* l1b   = (const float*)d_in[18];
    const float* l1bs  = (const float*)d_in[19];
    const float* l2g   = (const float*)d_in[20];
    const float* l2gs  = (const float*)d_in[21];
    const float* l2b   = (const float*)d_in[22];
    const float* l2bs  = (const float*)d_in[23];
    float* out = (float*)d_out;

    void* p;
    cudaGetSymbolAddress(&p, g_xdq);    float* xdq = (float*)p;
    cudaGetSymbolAddress(&p, g_hdq);    float* hdq = (float*)p;
    cudaGetSymbolAddress(&p, g_q);      float* qb  = (float*)p;
    cudaGetSymbolAddress(&p, g_k);      float* kb  = (float*)p;
    cudaGetSymbolAddress(&p, g_v);      float* vb  = (float*)p;
    cudaGetSymbolAddress(&p, g_scores); float* sc  = (float*)p;
    cudaGetSymbolAddress(&p, g_ctx);    float* ctx = (float*)p;
    cudaGetSymbolAddress(&p, g_tmp);    float* tmp = (float*)p;
    cudaGetSymbolAddress(&p, g_x1);     float* x1  = (float*)p;
    cudaGetSymbolAddress(&p, g_h);      float* hb  = (float*)p;
    cudaGetSymbolAddress(&p, g_ffn);    float* ffn = (float*)p;

    const float E5MAX = 57344.0f, E4MAX = 448.0f;
    const float INV_SQRT_HD = 0.08838834764831845f;

    // 1. qdq x (E5M2)
    qdq_kernel<<<(Mrows * Cdim / 128) / 8, 256>>>(x, xdq, E5MAX, 0);

    // 2. QKV projections
    dim3 gl(Cdim / 128, Mrows / 128, 1);
    gemm_nt<<<gl, 128>>>(xdq, wq, qb, Cdim, Cdim, Cdim, Cdim,
                         1, 0, 0, 0, 0, 0, 0, qs, nullptr, 0, 0);
    gemm_nt<<<gl, 128>>>(xdq, wk, kb, Cdim, Cdim, Cdim, Cdim,
                         1, 0, 0, 0, 0, 0, 0, ks, nullptr, 0, 0);
    gemm_nt<<<gl, 128>>>(xdq, wv, vb, Cdim, Cdim, Cdim, Cdim,
                         1, 0, 0, 0, 0, 0, 0, vs, nullptr, 0, 0);

    // 3. scores = Q @ K^T (causal tiles only)
    dim3 gsc(Tt / 128, Tt / 128, Bb * Hh);
    gemm_nt<<<gsc, 128>>>(qb, kb, sc, HDim, Cdim, Cdim, Tt,
                          Hh, (long long)Tt * Cdim, 128, (long long)Tt * Cdim, 128,
                          (long long)Hh * Tt * Tt, (long long)Tt * Tt,
                          nullptr, nullptr, 0, 1);

    // 4. masked softmax
    softmax_kernel<<<Bb * Hh * Tt, 256>>>(sc, mask, INV_SQRT_HD);

    // 5. ctx = attn @ V (K capped causally)
    dim3 gcx(1, Tt / 128, Bb * Hh);
    gemm_nn<<<gcx, 256>>>(sc, vb, ctx, Tt, Tt, Cdim, Cdim,
                          Hh, (long long)Hh * Tt * Tt, (long long)Tt * Tt,
                          (long long)Tt * Cdim, 128, (long long)Tt * Cdim, 128, 1);

    // 6. out projection
    qdq_kernel<<<(Mrows * Cdim / 128) / 8, 256>>>(ctx, xdq, E5MAX, 0);
    gemm_nt<<<gl, 128>>>(xdq, wo, tmp, Cdim, Cdim, Cdim, Cdim,
                         1, 0, 0, 0, 0, 0, 0, os_, nullptr, 0, 0);

    // 7. x1 = LN1(x + attn_out)
    addln_kernel<<<Mrows, 256>>>(x, tmp, x1, l1g, l1gs, l1b, l1bs);

    // 8. fc1 + bias + exact GELU
    qdq_kernel<<<(Mrows * Cdim / 128) / 8, 256>>>(x1, xdq, E4MAX, 1);
    dim3 gf1(MLPD / 128, Mrows / 128, 1);
    gemm_nt<<<gf1, 128>>>(xdq, fc1w, hb, Cdim, Cdim, Cdim, MLPD,
                          1, 0, 0, 0, 0, 0, 0, fc1s, fc1b, 1, 0);

    // 9. fc2 + bias
    qdq_kernel<<<(Mrows * MLPD / 128) / 8, 256>>>(hb, hdq, E4MAX, 1);
    dim3 gf2(Cdim / 128, Mrows / 128, 1);
    gemm_nt<<<gf2, 128>>>(hdq, fc2w, ffn, MLPD, MLPD, MLPD, Cdim,
                          1, 0, 0, 0, 0, 0, 0, fc2s, fc2b, 0, 0);

    // 10. out = LN2(x1 + ffn)
    addln_kernel<<<Mrows, 256>>>(x1, ffn, out, l2g, l2gs, l2b, l2bs);
}

// round 15
// speedup vs baseline: 1.1429x; 1.0520x over previous
#include <cuda_runtime.h>
#include <cuda_fp8.h>
#include <cuda_fp16.h>
#include <cstdint>
#include <math.h>

#define Bb 2
#define Tt 1024
#define Cdim 2048
#define Hh 16
#define HDim 128
#define MLPD 8192
#define Mrows (Bb * Tt)

__device__ float g_xdq[Mrows * Cdim];
__device__ float g_hdq[Mrows * MLPD];
__device__ float g_q[Mrows * Cdim];
__device__ float g_k[Mrows * Cdim];
__device__ float g_v[Mrows * Cdim];
__device__ float g_scores[(size_t)Bb * Hh * Tt * Tt];
__device__ float g_ctx[Mrows * Cdim];
__device__ float g_tmp[Mrows * Cdim];
__device__ float g_x1[Mrows * Cdim];
__device__ float g_h[Mrows * MLPD];
__device__ float g_ffn[Mrows * Cdim];

// ---------------------------------------------------------------------------
// Packed f32x2 helpers (B300 dual-lane fp32 FMA). Lane-wise IEEE fp32 fma ->
// bit-identical to scalar fmaf sequences.
// ---------------------------------------------------------------------------
typedef unsigned long long u64t;
__device__ __forceinline__ u64t pk2(float lo, float hi) {
    u64t d;
    asm("mov.b64 %0, {%1,%2};" : "=l"(d) : "f"(lo), "f"(hi));
    return d;
}
__device__ __forceinline__ void upk2(float& lo, float& hi, u64t d) {
    asm("mov.b64 {%0,%1}, %2;" : "=f"(lo), "=f"(hi) : "l"(d));
}
__device__ __forceinline__ void fma2(u64t& c, u64t a, u64t b) {
    asm("fma.rn.f32x2 %0, %1, %2, %0;" : "+l"(c) : "l"(a), "l"(b));
}

// ---------------------------------------------------------------------------
// fp32 quantize-dequantize (bit-identical to R1/R9)
// ---------------------------------------------------------------------------
__global__ void qdq_kernel(const float* __restrict__ in, float* __restrict__ out,
                           float fmax, int e4m3)
{
    int blk  = blockIdx.x * 8 + (threadIdx.x >> 5);
    int lane = threadIdx.x & 31;
    size_t base = (size_t)blk * 128 + (size_t)lane * 4;
    float4 v = *reinterpret_cast<const float4*>(in + base);
    float am = fmaxf(fmaxf(fabsf(v.x), fabsf(v.y)), fmaxf(fabsf(v.z), fabsf(v.w)));
    #pragma unroll
    for (int o = 16; o > 0; o >>= 1)
        am = fmaxf(am, __shfl_xor_sync(0xffffffffu, am, o));
    float s = fmaxf(am / fmax, 1e-12f);
    float r4[4]; float xin[4] = {v.x, v.y, v.z, v.w};
    #pragma unroll
    for (int i = 0; i < 4; i++) {
        float r = xin[i] / s;
        __nv_fp8_storage_t f8 = __nv_cvt_float_to_fp8(r, __NV_SATFINITE, e4m3 ? __NV_E4M3 : __NV_E5M2);
        __half_raw hr = __nv_cvt_fp8_to_halfraw(f8, e4m3 ? __NV_E4M3 : __NV_E5M2);
        r4[i] = __half2float(*reinterpret_cast<__half*>(&hr)) * s;
    }
    float4 o4 = {r4[0], r4[1], r4[2], r4[3]};
    *reinterpret_cast<float4*>(out + base) = o4;
}

// ---------------------------------------------------------------------------
// Double-buffered fp32 SGEMM NT: 128 threads, 16x8 per thread, BK=8, f32x2.
// B fragment split {tx*4, 64+tx*4}: 16-B-stride LDS -> conflict-free (2-phase
// minimum) instead of 4-way conflicted 32-B stride. Per-element k-order
// unchanged -> bit-identical. causal: skip tiles with n0 > m0+127.
// ---------------------------------------------------------------------------
__global__ void __launch_bounds__(128, 2)
gemm_nt(const float* __restrict__ A, const float* __restrict__ W, float* __restrict__ C,
        int K, int lda, int ldb, int ldc,
        int zdiv, long long sA1, long long sA2, long long sB1, long long sB2,
        long long sC1, long long sC2,
        const float* __restrict__ wscale, const float* __restrict__ bias,
        int act, int causal)
{
    __shared__ float As[2][8][132];
    __shared__ float Bs[2][8][132];
    int z = blockIdx.z;
    int z1 = z / zdiv, z2 = z % zdiv;
    A += z1 * sA1 + z2 * sA2;
    W += z1 * sB1 + z2 * sB2;
    C += z1 * sC1 + z2 * sC2;

    int m0 = blockIdx.y * 128, n0 = blockIdx.x * 128;
    if (causal && n0 > m0 + 127) return;

    int tid = threadIdx.x;
    int tx = tid & 15, ty = tid >> 4;          // ty: 0..7 (16 m-rows each)
    const float* gA = A + (size_t)(m0 + tid) * lda;   // loader: one row per thread
    const float* gB = W + (size_t)(n0 + tid) * ldb;

    u64t acc2[16][4];
    #pragma unroll
    for (int i = 0; i < 16; i++)
        #pragma unroll
        for (int j = 0; j < 4; j++) acc2[i][j] = 0ull;

    float4 av0 = *reinterpret_cast<const float4*>(gA);
    float4 av1 = *reinterpret_cast<const float4*>(gA + 4);
    float4 bv0 = *reinterpret_cast<const float4*>(gB);
    float4 bv1 = *reinterpret_cast<const float4*>(gB + 4);
    {
        float a8[8] = {av0.x, av0.y, av0.z, av0.w, av1.x, av1.y, av1.z, av1.w};
        float b8[8] = {bv0.x, bv0.y, bv0.z, bv0.w, bv1.x, bv1.y, bv1.z, bv1.w};
        #pragma unroll
        for (int q = 0; q < 8; q++) { As[0][q][tid] = a8[q]; Bs[0][q][tid] = b8[q]; }
    }
    __syncthreads();

    int nkt = K >> 3;
    for (int kt = 0; kt < nkt; kt++) {
        int cur = kt & 1;
        bool pf = (kt + 1) < nkt;
        if (pf) {
            const float* pA = gA + (kt + 1) * 8;
            const float* pB = gB + (kt + 1) * 8;
            av0 = *reinterpret_cast<const float4*>(pA);
            av1 = *reinterpret_cast<const float4*>(pA + 4);
            bv0 = *reinterpret_cast<const float4*>(pB);
            bv1 = *reinterpret_cast<const float4*>(pB + 4);
        }
        #pragma unroll
        for (int kk = 0; kk < 8; kk++) {
            float4 a0 = *reinterpret_cast<const float4*>(&As[cur][kk][ty * 16]);
            float4 a1 = *reinterpret_cast<const float4*>(&As[cur][kk][ty * 16 + 4]);
            float4 a2 = *reinterpret_cast<const float4*>(&As[cur][kk][ty * 16 + 8]);
            float4 a3 = *reinterpret_cast<const float4*>(&As[cur][kk][ty * 16 + 12]);
            float4 b0 = *reinterpret_cast<const float4*>(&Bs[cur][kk][tx * 4]);        // cols tx*4..+3
            float4 b1 = *reinterpret_cast<const float4*>(&Bs[cur][kk][64 + tx * 4]);   // cols 64+tx*4..+3
            float a[16] = {a0.x, a0.y, a0.z, a0.w, a1.x, a1.y, a1.z, a1.w,
                           a2.x, a2.y, a2.z, a2.w, a3.x, a3.y, a3.z, a3.w};
            u64t ad[16], bd[4];
            #pragma unroll
            for (int i = 0; i < 16; i++) ad[i] = pk2(a[i], a[i]);
            bd[0] = pk2(b0.x, b0.y); bd[1] = pk2(b0.z, b0.w);
            bd[2] = pk2(b1.x, b1.y); bd[3] = pk2(b1.z, b1.w);
            #pragma unroll
            for (int i = 0; i < 16; i++)
                #pragma unroll
                for (int j = 0; j < 4; j++) fma2(acc2[i][j], ad[i], bd[j]);
        }
        if (pf) {
            int nb = cur ^ 1;
            float a8[8] = {av0.x, av0.y, av0.z, av0.w, av1.x, av1.y, av1.z, av1.w};
            float b8[8] = {bv0.x, bv0.y, bv0.z, bv0.w, bv1.x, bv1.y, bv1.z, bv1.w};
            #pragma unroll
            for (int q = 0; q < 8; q++) { As[nb][q][tid] = a8[q]; Bs[nb][q][tid] = b8[q]; }
        }
        __syncthreads();
    }

    #pragma unroll
    for (int i = 0; i < 16; i++) {
        int m = m0 + ty * 16 + i;
        #pragma unroll
        for (int j = 0; j < 4; j++) {
            float vlo, vhi;
            upk2(vlo, vhi, acc2[i][j]);
            // j=0,1 -> cols tx*4 + {0,1},{2,3}; j=2,3 -> cols 64+tx*4 + {0,1},{2,3}
            int colbase = (j < 2) ? (tx * 4 + (j & 1) * 2) : (64 + tx * 4 + (j & 1) * 2);
            int n = n0 + colbase;
            float ws0 = wscale ? wscale[n >> 7] : 1.0f;
            float ws1 = wscale ? wscale[(n + 1) >> 7] : 1.0f;
            vlo *= ws0; vhi *= ws1;
            if (bias) { vlo += bias[n]; vhi += bias[n + 1]; }
            if (act) {
                vlo = 0.5f * vlo * (1.0f + erff(vlo * 0.7071067811865476f));
                vhi = 0.5f * vhi * (1.0f + erff(vhi * 0.7071067811865476f));
            }
            C[(size_t)m * ldc + n]     = vlo;
            C[(size_t)m * ldc + n + 1] = vhi;
        }
    }
}

// ---------------------------------------------------------------------------
// Double-buffered fp32 SGEMM NN (attn @ V), BK=8, f32x2, split B fragment.
// Exact causal K cap at m0+128.
// ---------------------------------------------------------------------------
__global__ void __launch_bounds__(256, 2)
gemm_nn(const float* __restrict__ A, const float* __restrict__ Bm, float* __restrict__ C,
        int K, int lda, int ldb, int ldc,
        int zdiv, long long sA1, long long sA2, long long sB1, long long sB2,
        long long sC1, long long sC2, int causal)
{
    __shared__ float As[2][8][132];
    __shared__ float Bs[2][8][132];
    int z = blockIdx.z;
    int z1 = z / zdiv, z2 = z % zdiv;
    A  += z1 * sA1 + z2 * sA2;
    Bm += z1 * sB1 + z2 * sB2;
    C  += z1 * sC1 + z2 * sC2;
    int tid = threadIdx.x;
    int tx = tid & 15, ty = tid >> 4;
    int m0 = blockIdx.y * 128, n0 = blockIdx.x * 128;
    int arow = tid >> 1, acol = (tid & 1) * 4;
    int brow = tid >> 5, bcol = (tid & 31) * 4;
    const float* gA = A + (size_t)(m0 + arow) * lda + acol;
    const float* gB = Bm + (size_t)brow * ldb + n0 + bcol;

    int Keff = causal ? (m0 + 128 < K ? m0 + 128 : K) : K;

    u64t acc2[8][4];
    #pragma unroll
    for (int i = 0; i < 8; i++)
        #pragma unroll
        for (int j = 0; j < 4; j++) acc2[i][j] = 0ull;

    float4 av = *reinterpret_cast<const float4*>(gA);
    float4 bv = *reinterpret_cast<const float4*>(gB);
    As[0][acol + 0][arow] = av.x; As[0][acol + 1][arow] = av.y;
    As[0][acol + 2][arow] = av.z; As[0][acol + 3][arow] = av.w;
    *reinterpret_cast<float4*>(&Bs[0][brow][bcol]) = bv;
    __syncthreads();

    int nkt = Keff >> 3;
    for (int kt = 0; kt < nkt; kt++) {
        int cur = kt & 1;
        bool pf = (kt + 1) < nkt;
        if (pf) {
            av = *reinterpret_cast<const float4*>(gA + (kt + 1) * 8);
            bv = *reinterpret_cast<const float4*>(gB + (size_t)(kt + 1) * 8 * ldb);
        }
        #pragma unroll
        for (int kk = 0; kk < 8; kk++) {
            float4 a0 = *reinterpret_cast<const float4*>(&As[cur][kk][ty * 8]);
            float4 a1 = *reinterpret_cast<const float4*>(&As[cur][kk][ty * 8 + 4]);
            float4 b0 = *reinterpret_cast<const float4*>(&Bs[cur][kk][tx * 4]);
            float4 b1 = *reinterpret_cast<const float4*>(&Bs[cur][kk][64 + tx * 4]);
            float a[8] = {a0.x, a0.y, a0.z, a0.w, a1.x, a1.y, a1.z, a1.w};
            u64t ad[8], bd[4];
            #pragma unroll
            for (int i = 0; i < 8; i++) ad[i] = pk2(a[i], a[i]);
            bd[0] = pk2(b0.x, b0.y); bd[1] = pk2(b0.z, b0.w);
            bd[2] = pk2(b1.x, b1.y); bd[3] = pk2(b1.z, b1.w);
            #pragma unroll
            for (int i = 0; i < 8; i++)
                #pragma unroll
                for (int j = 0; j < 4; j++) fma2(acc2[i][j], ad[i], bd[j]);
        }
        if (pf) {
            int nb = cur ^ 1;
            As[nb][acol + 0][arow] = av.x; As[nb][acol + 1][arow] = av.y;
            As[nb][acol + 2][arow] = av.z; As[nb][acol + 3][arow] = av.w;
            *reinterpret_cast<float4*>(&Bs[nb][brow][bcol]) = bv;
        }
        __syncthreads();
    }

    #pragma unroll
    for (int i = 0; i < 8; i++) {
        int m = m0 + ty * 8 + i;
        #pragma unroll
        for (int j = 0; j < 4; j++) {
            float vlo, vhi;
            upk2(vlo, vhi, acc2[i][j]);
            int colbase = (j < 2) ? (tx * 4 + (j & 1) * 2) : (64 + tx * 4 + (j & 1) * 2);
            int n = n0 + colbase;
            C[(size_t)m * ldc + n]     = vlo;
            C[(size_t)m * ldc + n + 1] = vhi;
        }
    }
}

// ---------------------------------------------------------------------------
// Causal-masked softmax — verbatim R1/R9
// ---------------------------------------------------------------------------
__global__ void softmax_kernel(float* __restrict__ S, const int* __restrict__ mask, float scale)
{
    int row = blockIdx.x;
    int q = row % Tt;
    int b = row / (Hh * Tt);
    float* sr = S + (size_t)row * Tt;
    const int* mr = mask + ((size_t)b * Tt + q) * Tt;
    int tid = threadIdx.x;
    __shared__ float red[256];
    float vals[4];
    float lmax = -INFINITY;
    #pragma unroll
    for (int it = 0; it < 4; it++) {
        int i = tid + it * 256;
        float v = mr[i] ? sr[i] * scale : -INFINITY;
        vals[it] = v;
        lmax = fmaxf(lmax, v);
    }
    red[tid] = lmax; __syncthreads();
    for (int o = 128; o > 0; o >>= 1) {
        if (tid < o) red[tid] = fmaxf(red[tid], red[tid + o]);
        __syncthreads();
    }
    float mx = red[0];
    __syncthreads();
    float lsum = 0.0f;
    #pragma unroll
    for (int it = 0; it < 4; it++) {
        float e = expf(vals[it] - mx);
        vals[it] = e;
        lsum += e;
    }
    red[tid] = lsum; __syncthreads();
    for (int o = 128; o > 0; o >>= 1) {
        if (tid < o) red[tid] += red[tid + o];
        __syncthreads();
    }
    float inv = 1.0f / red[0];
    #pragma unroll
    for (int it = 0; it < 4; it++) {
        int i = tid + it * 256;
        sr[i] = vals[it] * inv;
    }
}

// ---------------------------------------------------------------------------
// LayerNorm(x + y) — verbatim R1/R9
// ---------------------------------------------------------------------------
__global__ void addln_kernel(const float* __restrict__ x, const float* __restrict__ y,
                             float* __restrict__ out,
                             const float* __restrict__ g, const float* __restrict__ gs,
                             const float* __restrict__ b, const float* __restrict__ bs)
{
    int row = blockIdx.x;
    const float* xr = x + (size_t)row * Cdim;
    const float* yr = y + (size_t)row * Cdim;
    float* outr = out + (size_t)row * Cdim;
    __shared__ float buf[Cdim];
    __shared__ float red[256];
    int tid = threadIdx.x;
    float lsum = 0.0f;
    #pragma unroll
    for (int it = 0; it < Cdim / 256; it++) {
        int i = tid + it * 256;
        float v = xr[i] + yr[i];
        buf[i] = v;
        lsum += v;
    }
    red[tid] = lsum; __syncthreads();
    for (int o = 128; o > 0; o >>= 1) {
        if (tid < o) red[tid] += red[tid + o];
        __syncthreads();
    }
    float mean = red[0] * (1.0f / Cdim);
    __syncthreads();
    float lvar = 0.0f;
    #pragma unroll
    for (int it = 0; it < Cdim / 256; it++) {
        int i = tid + it * 256;
        float d = buf[i] - mean;
        lvar += d * d;
    }
    red[tid] = lvar; __syncthreads();
    for (int o = 128; o > 0; o >>= 1) {
        if (tid < o) red[tid] += red[tid + o];
        __syncthreads();
    }
    float rstd = rsqrtf(red[0] * (1.0f / Cdim) + 1e-5f);
    #pragma unroll
    for (int it = 0; it < Cdim / 256; it++) {
        int i = tid + it * 256;
        float d = (buf[i] - mean) * rstd;
        outr[i] = d * (g[i] * gs[i >> 7]) + b[i] * bs[i >> 7];
    }
}

// ---------------------------------------------------------------------------
// Launch pipeline
// ---------------------------------------------------------------------------
extern "C" void kernel_launch(void* const* d_in, const int* in_sizes, int n_in,
                              void* d_out, int out_size)
{
    const float* x     = (const float*)d_in[0];
    const int*   mask  = (const int*)  d_in[1];
    const float* wq    = (const float*)d_in[2];
    const float* qs    = (const float*)d_in[3];
    const float* wk    = (const float*)d_in[4];
    const float* ks    = (const float*)d_in[5];
    const float* wv    = (const float*)d_in[6];
    const float* vs    = (const float*)d_in[7];
    const float* wo    = (const float*)d_in[8];
    const float* os_   = (const float*)d_in[9];
    const float* fc1w  = (const float*)d_in[10];
    const float* fc1s  = (const float*)d_in[11];
    const float* fc1b  = (const float*)d_in[12];
    const float* fc2w  = (const float*)d_in[13];
    const float* fc2s  = (const float*)d_in[14];
    const float* fc2b  = (const float*)d_in[15];
    const float* l1g   = (const float*)d_in[16];
    const float* l1gs  = (const float*)d_in[17];
    const float* l1b   = (const float*)d_in[18];
    const float* l1bs  = (const float*)d_in[19];
    const float* l2g   = (const float*)d_in[20];
    const float* l2gs  = (const float*)d_in[21];
    const float* l2b   = (const float*)d_in[22];
    const float* l2bs  = (const float*)d_in[23];
    float* out = (float*)d_out;

    void* p;
    cudaGetSymbolAddress(&p, g_xdq);    float* xdq = (float*)p;
    cudaGetSymbolAddress(&p, g_hdq);    float* hdq = (float*)p;
    cudaGetSymbolAddress(&p, g_q);      float* qb  = (float*)p;
    cudaGetSymbolAddress(&p, g_k);      float* kb  = (float*)p;
    cudaGetSymbolAddress(&p, g_v);      float* vb  = (float*)p;
    cudaGetSymbolAddress(&p, g_scores); float* sc  = (float*)p;
    cudaGetSymbolAddress(&p, g_ctx);    float* ctx = (float*)p;
    cudaGetSymbolAddress(&p, g_tmp);    float* tmp = (float*)p;
    cudaGetSymbolAddress(&p, g_x1);     float* x1  = (float*)p;
    cudaGetSymbolAddress(&p, g_h);      float* hb  = (float*)p;
    cudaGetSymbolAddress(&p, g_ffn);    float* ffn = (float*)p;

    const float E5MAX = 57344.0f, E4MAX = 448.0f;
    const float INV_SQRT_HD = 0.08838834764831845f;

    // 1. qdq x (E5M2)
    qdq_kernel<<<(Mrows * Cdim / 128) / 8, 256>>>(x, xdq, E5MAX, 0);

    // 2. QKV projections
    dim3 gl(Cdim / 128, Mrows / 128, 1);
    gemm_nt<<<gl, 128>>>(xdq, wq, qb, Cdim, Cdim, Cdim, Cdim,
                         1, 0, 0, 0, 0, 0, 0, qs, nullptr, 0, 0);
    gemm_nt<<<gl, 128>>>(xdq, wk, kb, Cdim, Cdim, Cdim, Cdim,
                         1, 0, 0, 0, 0, 0, 0, ks, nullptr, 0, 0);
    gemm_nt<<<gl, 128>>>(xdq, wv, vb, Cdim, Cdim, Cdim, Cdim,
                         1, 0, 0, 0, 0, 0, 0, vs, nullptr, 0, 0);

    // 3. scores = Q @ K^T (causal tiles only)
    dim3 gsc(Tt / 128, Tt / 128, Bb * Hh);
    gemm_nt<<<gsc, 128>>>(qb, kb, sc, HDim, Cdim, Cdim, Tt,
                          Hh, (long long)Tt * Cdim, 128, (long long)Tt * Cdim, 128,
                          (long long)Hh * Tt * Tt, (long long)Tt * Tt,
                          nullptr, nullptr, 0, 1);

    // 4. masked softmax
    softmax_kernel<<<Bb * Hh * Tt, 256>>>(sc, mask, INV_SQRT_HD);

    // 5. ctx = attn @ V (K capped causally)
    dim3 gcx(1, Tt / 128, Bb * Hh);
    gemm_nn<<<gcx, 256>>>(sc, vb, ctx, Tt, Tt, Cdim, Cdim,
                          Hh, (long long)Hh * Tt * Tt, (long long)Tt * Tt,
                          (long long)Tt * Cdim, 128, (long long)Tt * Cdim, 128, 1);

    // 6. out projection
    qdq_kernel<<<(Mrows * Cdim / 128) / 8, 256>>>(ctx, xdq, E5MAX, 0);
    gemm_nt<<<gl, 128>>>(xdq, wo, tmp, Cdim, Cdim, Cdim, Cdim,
                         1, 0, 0, 0, 0, 0, 0, os_, nullptr, 0, 0);

    // 7. x1 = LN1(x + attn_out)
    addln_kernel<<<Mrows, 256>>>(x, tmp, x1, l1g, l1gs, l1b, l1bs);

    // 8. fc1 + bias + exact GELU
    qdq_kernel<<<(Mrows * Cdim / 128) / 8, 256>>>(x1, xdq, E4MAX, 1);
    dim3 gf1(MLPD / 128, Mrows / 128, 1);
    gemm_nt<<<gf1, 128>>>(xdq, fc1w, hb, Cdim, Cdim, Cdim, MLPD,
                          1, 0, 0, 0, 0, 0, 0, fc1s, fc1b, 1, 0);

    // 9. fc2 + bias
    qdq_kernel<<<(Mrows * MLPD / 128) / 8, 256>>>(hb, hdq, E4MAX, 1);
    dim3 gf2(Cdim / 128, Mrows / 128, 1);
    gemm_nt<<<gf2, 128>>>(hdq, fc2w, ffn, MLPD, MLPD, MLPD, Cdim,
                          1, 0, 0, 0, 0, 0, 0, fc2s, fc2b, 0, 0);

    // 10. out = LN2(x1 + ffn)
    addln_kernel<<<Mrows, 256>>>(x1, ffn, out, l2g, l2gs, l2b, l2bs);
}

// round 16
// speedup vs baseline: 1.1635x; 1.0180x over previous
#include <cuda_runtime.h>
#include <cuda_fp8.h>
#include <cuda_fp16.h>
#include <cstdint>
#include <math.h>

#define Bb 2
#define Tt 1024
#define Cdim 2048
#define Hh 16
#define HDim 128
#define MLPD 8192
#define Mrows (Bb * Tt)

__device__ float g_xdq[Mrows * Cdim];
__device__ float g_hdq[Mrows * MLPD];
__device__ float g_q[Mrows * Cdim];
__device__ float g_k[Mrows * Cdim];
__device__ float g_v[Mrows * Cdim];
__device__ float g_scores[(size_t)Bb * Hh * Tt * Tt];
__device__ float g_ctx[Mrows * Cdim];
__device__ float g_tmp[Mrows * Cdim];
__device__ float g_x1[Mrows * Cdim];
__device__ float g_h[Mrows * MLPD];
__device__ float g_ffn[Mrows * Cdim];

// ---------------------------------------------------------------------------
// Packed f32x2 helpers (B300 dual-lane fp32 FMA). Lane-wise IEEE fp32 fma ->
// bit-identical to scalar fmaf sequences.
// ---------------------------------------------------------------------------
typedef unsigned long long u64t;
__device__ __forceinline__ u64t pk2(float lo, float hi) {
    u64t d;
    asm("mov.b64 %0, {%1,%2};" : "=l"(d) : "f"(lo), "f"(hi));
    return d;
}
__device__ __forceinline__ void upk2(float& lo, float& hi, u64t d) {
    asm("mov.b64 {%0,%1}, %2;" : "=f"(lo), "=f"(hi) : "l"(d));
}
__device__ __forceinline__ void fma2(u64t& c, u64t a, u64t b) {
    asm("fma.rn.f32x2 %0, %1, %2, %0;" : "+l"(c) : "l"(a), "l"(b));
}

// ---------------------------------------------------------------------------
// fp32 quantize-dequantize (bit-identical to R1/R9)
// ---------------------------------------------------------------------------
__global__ void qdq_kernel(const float* __restrict__ in, float* __restrict__ out,
                           float fmax, int e4m3)
{
    int blk  = blockIdx.x * 8 + (threadIdx.x >> 5);
    int lane = threadIdx.x & 31;
    size_t base = (size_t)blk * 128 + (size_t)lane * 4;
    float4 v = *reinterpret_cast<const float4*>(in + base);
    float am = fmaxf(fmaxf(fabsf(v.x), fabsf(v.y)), fmaxf(fabsf(v.z), fabsf(v.w)));
    #pragma unroll
    for (int o = 16; o > 0; o >>= 1)
        am = fmaxf(am, __shfl_xor_sync(0xffffffffu, am, o));
    float s = fmaxf(am / fmax, 1e-12f);
    float r4[4]; float xin[4] = {v.x, v.y, v.z, v.w};
    #pragma unroll
    for (int i = 0; i < 4; i++) {
        float r = xin[i] / s;
        __nv_fp8_storage_t f8 = __nv_cvt_float_to_fp8(r, __NV_SATFINITE, e4m3 ? __NV_E4M3 : __NV_E5M2);
        __half_raw hr = __nv_cvt_fp8_to_halfraw(f8, e4m3 ? __NV_E4M3 : __NV_E5M2);
        r4[i] = __half2float(*reinterpret_cast<__half*>(&hr)) * s;
    }
    float4 o4 = {r4[0], r4[1], r4[2], r4[3]};
    *reinterpret_cast<float4*>(out + base) = o4;
}

// ---------------------------------------------------------------------------
// Double-buffered fp32 SGEMM NT: 128 threads, 16x8 per thread, BK=8, f32x2.
// FFMA2 pairs along M: A operand = natural LDS register pair (0 movs);
// only 8 B-dup movs per kk. B fragment split {tx*4, 64+tx*4} (conflict-free).
// Per-element k-order unchanged -> bit-identical.
// ---------------------------------------------------------------------------
__global__ void __launch_bounds__(128, 2)
gemm_nt(const float* __restrict__ A, const float* __restrict__ W, float* __restrict__ C,
        int K, int lda, int ldb, int ldc,
        int zdiv, long long sA1, long long sA2, long long sB1, long long sB2,
        long long sC1, long long sC2,
        const float* __restrict__ wscale, const float* __restrict__ bias,
        int act, int causal)
{
    __shared__ float As[2][8][132];
    __shared__ float Bs[2][8][132];
    int z = blockIdx.z;
    int z1 = z / zdiv, z2 = z % zdiv;
    A += z1 * sA1 + z2 * sA2;
    W += z1 * sB1 + z2 * sB2;
    C += z1 * sC1 + z2 * sC2;

    int m0 = blockIdx.y * 128, n0 = blockIdx.x * 128;
    if (causal && n0 > m0 + 127) return;

    int tid = threadIdx.x;
    int tx = tid & 15, ty = tid >> 4;          // ty: 0..7 (16 m-rows each)
    const float* gA = A + (size_t)(m0 + tid) * lda;
    const float* gB = W + (size_t)(n0 + tid) * ldb;

    // acc2[p][j]: m-pair p (rows 2p,2p+1 of this thread's 16), column j
    u64t acc2[8][8];
    #pragma unroll
    for (int p = 0; p < 8; p++)
        #pragma unroll
        for (int j = 0; j < 8; j++) acc2[p][j] = 0ull;

    float4 av0 = *reinterpret_cast<const float4*>(gA);
    float4 av1 = *reinterpret_cast<const float4*>(gA + 4);
    float4 bv0 = *reinterpret_cast<const float4*>(gB);
    float4 bv1 = *reinterpret_cast<const float4*>(gB + 4);
    {
        float a8[8] = {av0.x, av0.y, av0.z, av0.w, av1.x, av1.y, av1.z, av1.w};
        float b8[8] = {bv0.x, bv0.y, bv0.z, bv0.w, bv1.x, bv1.y, bv1.z, bv1.w};
        #pragma unroll
        for (int q = 0; q < 8; q++) { As[0][q][tid] = a8[q]; Bs[0][q][tid] = b8[q]; }
    }
    __syncthreads();

    int nkt = K >> 3;
    for (int kt = 0; kt < nkt; kt++) {
        int cur = kt & 1;
        bool pf = (kt + 1) < nkt;
        if (pf) {
            const float* pA = gA + (kt + 1) * 8;
            const float* pB = gB + (kt + 1) * 8;
            av0 = *reinterpret_cast<const float4*>(pA);
            av1 = *reinterpret_cast<const float4*>(pA + 4);
            bv0 = *reinterpret_cast<const float4*>(pB);
            bv1 = *reinterpret_cast<const float4*>(pB + 4);
        }
        #pragma unroll
        for (int kk = 0; kk < 8; kk++) {
            float4 a0 = *reinterpret_cast<const float4*>(&As[cur][kk][ty * 16]);
            float4 a1 = *reinterpret_cast<const float4*>(&As[cur][kk][ty * 16 + 4]);
            float4 a2 = *reinterpret_cast<const float4*>(&As[cur][kk][ty * 16 + 8]);
            float4 a3 = *reinterpret_cast<const float4*>(&As[cur][kk][ty * 16 + 12]);
            float4 b0 = *reinterpret_cast<const float4*>(&Bs[cur][kk][tx * 4]);
            float4 b1 = *reinterpret_cast<const float4*>(&Bs[cur][kk][64 + tx * 4]);
            // A pairs: natural adjacent-register pairs (mov-eliminable)
            u64t ad[8];
            ad[0] = pk2(a0.x, a0.y); ad[1] = pk2(a0.z, a0.w);
            ad[2] = pk2(a1.x, a1.y); ad[3] = pk2(a1.z, a1.w);
            ad[4] = pk2(a2.x, a2.y); ad[5] = pk2(a2.z, a2.w);
            ad[6] = pk2(a3.x, a3.y); ad[7] = pk2(a3.z, a3.w);
            // B dups: 8 unavoidable movs
            u64t bd[8];
            bd[0] = pk2(b0.x, b0.x); bd[1] = pk2(b0.y, b0.y);
            bd[2] = pk2(b0.z, b0.z); bd[3] = pk2(b0.w, b0.w);
            bd[4] = pk2(b1.x, b1.x); bd[5] = pk2(b1.y, b1.y);
            bd[6] = pk2(b1.z, b1.z); bd[7] = pk2(b1.w, b1.w);
            #pragma unroll
            for (int p = 0; p < 8; p++)
                #pragma unroll
                for (int j = 0; j < 8; j++) fma2(acc2[p][j], ad[p], bd[j]);
        }
        if (pf) {
            int nb = cur ^ 1;
            float a8[8] = {av0.x, av0.y, av0.z, av0.w, av1.x, av1.y, av1.z, av1.w};
            float b8[8] = {bv0.x, bv0.y, bv0.z, bv0.w, bv1.x, bv1.y, bv1.z, bv1.w};
            #pragma unroll
            for (int q = 0; q < 8; q++) { As[nb][q][tid] = a8[q]; Bs[nb][q][tid] = b8[q]; }
        }
        __syncthreads();
    }

    // epilogue: per m-pair, two rows; each row writes two float4 groups
    #pragma unroll
    for (int p = 0; p < 8; p++) {
        #pragma unroll
        for (int g = 0; g < 2; g++) {
            int ncol = n0 + g * 64 + tx * 4;
            float ws = wscale ? wscale[ncol >> 7] : 1.0f;   // 4 cols share one 128-block
            float r0[4], r1[4];
            #pragma unroll
            for (int c = 0; c < 4; c++) {
                float vlo, vhi;
                upk2(vlo, vhi, acc2[p][g * 4 + c]);
                vlo *= ws; vhi *= ws;
                if (bias) { float bb = bias[ncol + c]; vlo += bb; vhi += bb; }
                if (act) {
                    vlo = 0.5f * vlo * (1.0f + erff(vlo * 0.7071067811865476f));
                    vhi = 0.5f * vhi * (1.0f + erff(vhi * 0.7071067811865476f));
                }
                r0[c] = vlo; r1[c] = vhi;
            }
            int m = m0 + ty * 16 + p * 2;
            *reinterpret_cast<float4*>(C + (size_t)m * ldc + ncol)       = *reinterpret_cast<float4*>(r0);
            *reinterpret_cast<float4*>(C + (size_t)(m + 1) * ldc + ncol) = *reinterpret_cast<float4*>(r1);
        }
    }
}

// ---------------------------------------------------------------------------
// Double-buffered fp32 SGEMM NN (attn @ V), BK=8, f32x2, m-paired FFMA2.
// Exact causal K cap at m0+128.
// ---------------------------------------------------------------------------
__global__ void __launch_bounds__(256, 2)
gemm_nn(const float* __restrict__ A, const float* __restrict__ Bm, float* __restrict__ C,
        int K, int lda, int ldb, int ldc,
        int zdiv, long long sA1, long long sA2, long long sB1, long long sB2,
        long long sC1, long long sC2, int causal)
{
    __shared__ float As[2][8][132];
    __shared__ float Bs[2][8][132];
    int z = blockIdx.z;
    int z1 = z / zdiv, z2 = z % zdiv;
    A  += z1 * sA1 + z2 * sA2;
    Bm += z1 * sB1 + z2 * sB2;
    C  += z1 * sC1 + z2 * sC2;
    int tid = threadIdx.x;
    int tx = tid & 15, ty = tid >> 4;
    int m0 = blockIdx.y * 128, n0 = blockIdx.x * 128;
    int arow = tid >> 1, acol = (tid & 1) * 4;
    int brow = tid >> 5, bcol = (tid & 31) * 4;
    const float* gA = A + (size_t)(m0 + arow) * lda + acol;
    const float* gB = Bm + (size_t)brow * ldb + n0 + bcol;

    int Keff = causal ? (m0 + 128 < K ? m0 + 128 : K) : K;

    u64t acc2[4][8];
    #pragma unroll
    for (int p = 0; p < 4; p++)
        #pragma unroll
        for (int j = 0; j < 8; j++) acc2[p][j] = 0ull;

    float4 av = *reinterpret_cast<const float4*>(gA);
    float4 bv = *reinterpret_cast<const float4*>(gB);
    As[0][acol + 0][arow] = av.x; As[0][acol + 1][arow] = av.y;
    As[0][acol + 2][arow] = av.z; As[0][acol + 3][arow] = av.w;
    *reinterpret_cast<float4*>(&Bs[0][brow][bcol]) = bv;
    __syncthreads();

    int nkt = Keff >> 3;
    for (int kt = 0; kt < nkt; kt++) {
        int cur = kt & 1;
        bool pf = (kt + 1) < nkt;
        if (pf) {
            av = *reinterpret_cast<const float4*>(gA + (kt + 1) * 8);
            bv = *reinterpret_cast<const float4*>(gB + (size_t)(kt + 1) * 8 * ldb);
        }
        #pragma unroll
        for (int kk = 0; kk < 8; kk++) {
            float4 a0 = *reinterpret_cast<const float4*>(&As[cur][kk][ty * 8]);
            float4 a1 = *reinterpret_cast<const float4*>(&As[cur][kk][ty * 8 + 4]);
            float4 b0 = *reinterpret_cast<const float4*>(&Bs[cur][kk][tx * 4]);
            float4 b1 = *reinterpret_cast<const float4*>(&Bs[cur][kk][64 + tx * 4]);
            u64t ad[4];
            ad[0] = pk2(a0.x, a0.y); ad[1] = pk2(a0.z, a0.w);
            ad[2] = pk2(a1.x, a1.y); ad[3] = pk2(a1.z, a1.w);
            u64t bd[8];
            bd[0] = pk2(b0.x, b0.x); bd[1] = pk2(b0.y, b0.y);
            bd[2] = pk2(b0.z, b0.z); bd[3] = pk2(b0.w, b0.w);
            bd[4] = pk2(b1.x, b1.x); bd[5] = pk2(b1.y, b1.y);
            bd[6] = pk2(b1.z, b1.z); bd[7] = pk2(b1.w, b1.w);
            #pragma unroll
            for (int p = 0; p < 4; p++)
                #pragma unroll
                for (int j = 0; j < 8; j++) fma2(acc2[p][j], ad[p], bd[j]);
        }
        if (pf) {
            int nb = cur ^ 1;
            As[nb][acol + 0][arow] = av.x; As[nb][acol + 1][arow] = av.y;
            As[nb][acol + 2][arow] = av.z; As[nb][acol + 3][arow] = av.w;
            *reinterpret_cast<float4*>(&Bs[nb][brow][bcol]) = bv;
        }
        __syncthreads();
    }

    #pragma unroll
    for (int p = 0; p < 4; p++) {
        #pragma unroll
        for (int g = 0; g < 2; g++) {
            int ncol = n0 + g * 64 + tx * 4;
            float r0[4], r1[4];
            #pragma unroll
            for (int c = 0; c < 4; c++) {
                float vlo, vhi;
                upk2(vlo, vhi, acc2[p][g * 4 + c]);
                r0[c] = vlo; r1[c] = vhi;
            }
            int m = m0 + ty * 8 + p * 2;
            *reinterpret_cast<float4*>(C + (size_t)m * ldc + ncol)       = *reinterpret_cast<float4*>(r0);
            *reinterpret_cast<float4*>(C + (size_t)(m + 1) * ldc + ncol) = *reinterpret_cast<float4*>(r1);
        }
    }
}

// ---------------------------------------------------------------------------
// Causal-masked softmax — verbatim R1/R9
// ---------------------------------------------------------------------------
__global__ void softmax_kernel(float* __restrict__ S, const int* __restrict__ mask, float scale)
{
    int row = blockIdx.x;
    int q = row % Tt;
    int b = row / (Hh * Tt);
    float* sr = S + (size_t)row * Tt;
    const int* mr = mask + ((size_t)b * Tt + q) * Tt;
    int tid = threadIdx.x;
    __shared__ float red[256];
    float vals[4];
    float lmax = -INFINITY;
    #pragma unroll
    for (int it = 0; it < 4; it++) {
        int i = tid + it * 256;
        float v = mr[i] ? sr[i] * scale : -INFINITY;
        vals[it] = v;
        lmax = fmaxf(lmax, v);
    }
    red[tid] = lmax; __syncthreads();
    for (int o = 128; o > 0; o >>= 1) {
        if (tid < o) red[tid] = fmaxf(red[tid], red[tid + o]);
        __syncthreads();
    }
    float mx = red[0];
    __syncthreads();
    float lsum = 0.0f;
    #pragma unroll
    for (int it = 0; it < 4; it++) {
        float e = expf(vals[it] - mx);
        vals[it] = e;
        lsum += e;
    }
    red[tid] = lsum; __syncthreads();
    for (int o = 128; o > 0; o >>= 1) {
        if (tid < o) red[tid] += red[tid + o];
        __syncthreads();
    }
    float inv = 1.0f / red[0];
    #pragma unroll
    for (int it = 0; it < 4; it++) {
        int i = tid + it * 256;
        sr[i] = vals[it] * inv;
    }
}

// ---------------------------------------------------------------------------
// LayerNorm(x + y) — verbatim R1/R9
// ---------------------------------------------------------------------------
__global__ void addln_kernel(const float* __restrict__ x, const float* __restrict__ y,
                             float* __restrict__ out,
                             const float* __restrict__ g, const float* __restrict__ gs,
                             const float* __restrict__ b, const float* __restrict__ bs)
{
    int row = blockIdx.x;
    const float* xr = x + (size_t)row * Cdim;
    const float* yr = y + (size_t)row * Cdim;
    float* outr = out + (size_t)row * Cdim;
    __shared__ float buf[Cdim];
    __shared__ float red[256];
    int tid = threadIdx.x;
    float lsum = 0.0f;
    #pragma unroll
    for (int it = 0; it < Cdim / 256; it++) {
        int i = tid + it * 256;
        float v = xr[i] + yr[i];
        buf[i] = v;
        lsum += v;
    }
    red[tid] = lsum; __syncthreads();
    for (int o = 128; o > 0; o >>= 1) {
        if (tid < o) red[tid] += red[tid + o];
        __syncthreads();
    }
    float mean = red[0] * (1.0f / Cdim);
    __syncthreads();
    float lvar = 0.0f;
    #pragma unroll
    for (int it = 0; it < Cdim / 256; it++) {
        int i = tid + it * 256;
        float d = buf[i] - mean;
        lvar += d * d;
    }
    red[tid] = lvar; __syncthreads();
    for (int o = 128; o > 0; o >>= 1) {
        if (tid < o) red[tid] += red[tid + o];
        __syncthreads();
    }
    float rstd = rsqrtf(red[0] * (1.0f / Cdim) + 1e-5f);
    #pragma unroll
    for (int it = 0; it < Cdim / 256; it++) {
        int i = tid + it * 256;
        float d = (buf[i] - mean) * rstd;
        outr[i] = d * (g[i] * gs[i >> 7]) + b[i] * bs[i >> 7];
    }
}

// ---------------------------------------------------------------------------
// Launch pipeline
// ---------------------------------------------------------------------------
extern "C" void kernel_launch(void* const* d_in, const int* in_sizes, int n_in,
                              void* d_out, int out_size)
{
    const float* x     = (const float*)d_in[0];
    const int*   mask  = (const int*)  d_in[1];
    const float* wq    = (const float*)d_in[2];
    const float* qs    = (const float*)d_in[3];
    const float* wk    = (const float*)d_in[4];
    const float* ks    = (const float*)d_in[5];
    const float* wv    = (const float*)d_in[6];
    const float* vs    = (const float*)d_in[7];
    const float* wo    = (const float*)d_in[8];
    const float* os_   = (const float*)d_in[9];
    const float* fc1w  = (const float*)d_in[10];
    const float* fc1s  = (const float*)d_in[11];
    const float* fc1b  = (const float*)d_in[12];
    const float* fc2w  = (const float*)d_in[13];
    const float* fc2s  = (const float*)d_in[14];
    const float* fc2b  = (const float*)d_in[15];
    const float* l1g   = (const float*)d_in[16];
    const float* l1gs  = (const float*)d_in[17];
    const float* l1b   = (const float*)d_in[18];
    const float* l1bs  = (const float*)d_in[19];
    const float* l2g   = (const float*)d_in[20];
    const float* l2gs  = (const float*)d_in[21];
    const float* l2b   = (const float*)d_in[22];
    const float* l2bs  = (const float*)d_in[23];
    float* out = (float*)d_out;

    void* p;
    cudaGetSymbolAddress(&p, g_xdq);    float* xdq = (float*)p;
    cudaGetSymbolAddress(&p, g_hdq);    float* hdq = (float*)p;
    cudaGetSymbolAddress(&p, g_q);      float* qb  = (float*)p;
    cudaGetSymbolAddress(&p, g_k);      float* kb  = (float*)p;
    cudaGetSymbolAddress(&p, g_v);      float* vb  = (float*)p;
    cudaGetSymbolAddress(&p, g_scores); float* sc  = (float*)p;
    cudaGetSymbolAddress(&p, g_ctx);    float* ctx = (float*)p;
    cudaGetSymbolAddress(&p, g_tmp);    float* tmp = (float*)p;
    cudaGetSymbolAddress(&p, g_x1);     float* x1  = (float*)p;
    cudaGetSymbolAddress(&p, g_h);      float* hb  = (float*)p;
    cudaGetSymbolAddress(&p, g_ffn);    float* ffn = (float*)p;

    const float E5MAX = 57344.0f, E4MAX = 448.0f;
    const float INV_SQRT_HD = 0.08838834764831845f;

    // 1. qdq x (E5M2)
    qdq_kernel<<<(Mrows * Cdim / 128) / 8, 256>>>(x, xdq, E5MAX, 0);

    // 2. QKV projections
    dim3 gl(Cdim / 128, Mrows / 128, 1);
    gemm_nt<<<gl, 128>>>(xdq, wq, qb, Cdim, Cdim, Cdim, Cdim,
                         1, 0, 0, 0, 0, 0, 0, qs, nullptr, 0, 0);
    gemm_nt<<<gl, 128>>>(xdq, wk, kb, Cdim, Cdim, Cdim, Cdim,
                         1, 0, 0, 0, 0, 0, 0, ks, nullptr, 0, 0);
    gemm_nt<<<gl, 128>>>(xdq, wv, vb, Cdim, Cdim, Cdim, Cdim,
                         1, 0, 0, 0, 0, 0, 0, vs, nullptr, 0, 0);

    // 3. scores = Q @ K^T (causal tiles only)
    dim3 gsc(Tt / 128, Tt / 128, Bb * Hh);
    gemm_nt<<<gsc, 128>>>(qb, kb, sc, HDim, Cdim, Cdim, Tt,
                          Hh, (long long)Tt * Cdim, 128, (long long)Tt * Cdim, 128,
                          (long long)Hh * Tt * Tt, (long long)Tt * Tt,
                          nullptr, nullptr, 0, 1);

    // 4. masked softmax
    softmax_kernel<<<Bb * Hh * Tt, 256>>>(sc, mask, INV_SQRT_HD);

    // 5. ctx = attn @ V (K capped causally)
    dim3 gcx(1, Tt / 128, Bb * Hh);
    gemm_nn<<<gcx, 256>>>(sc, vb, ctx, Tt, Tt, Cdim, Cdim,
                          Hh, (long long)Hh * Tt * Tt, (long long)Tt * Tt,
                          (long long)Tt * Cdim, 128, (long long)Tt * Cdim, 128, 1);

    // 6. out projection
    qdq_kernel<<<(Mrows * Cdim / 128) / 8, 256>>>(ctx, xdq, E5MAX, 0);
    gemm_nt<<<gl, 128>>>(xdq, wo, tmp, Cdim, Cdim, Cdim, Cdim,
                         1, 0, 0, 0, 0, 0, 0, os_, nullptr, 0, 0);

    // 7. x1 = LN1(x + attn_out)
    addln_kernel<<<Mrows, 256>>>(x, tmp, x1, l1g, l1gs, l1b, l1bs);

    // 8. fc1 + bias + exact GELU
    qdq_kernel<<<(Mrows * Cdim / 128) / 8, 256>>>(x1, xdq, E4MAX, 1);
    dim3 gf1(MLPD / 128, Mrows / 128, 1);
    gemm_nt<<<gf1, 128>>>(xdq, fc1w, hb, Cdim, Cdim, Cdim, MLPD,
                          1, 0, 0, 0, 0, 0, 0, fc1s, fc1b, 1, 0);

    // 9. fc2 + bias
    qdq_kernel<<<(Mrows * MLPD / 128) / 8, 256>>>(hb, hdq, E4MAX, 1);
    dim3 gf2(Cdim / 128, Mrows / 128, 1);
    gemm_nt<<<gf2, 128>>>(hdq, fc2w, ffn, MLPD, MLPD, MLPD, Cdim,
                          1, 0, 0, 0, 0, 0, 0, fc2s, fc2b, 0, 0);

    // 10. out = LN2(x1 + ffn)
    addln_kernel<<<Mrows, 256>>>(x1, ffn, out, l2g, l2gs, l2b, l2bs);
}

// round 17
// speedup vs baseline: 1.4822x; 1.2739x over previous
#include <cuda_runtime.h>
#include <cuda_fp8.h>
#include <cuda_fp16.h>
#include <cstdint>
#include <math.h>

#define Bb 2
#define Tt 1024
#define Cdim 2048
#define Hh 16
#define HDim 128
#define MLPD 8192
#define Mrows (Bb * Tt)

__device__ float g_xdq[Mrows * Cdim];
__device__ float g_q[Mrows * Cdim];
__device__ float g_k[Mrows * Cdim];
__device__ float g_v[Mrows * Cdim];
__device__ float g_scores[(size_t)Bb * Hh * Tt * Tt];
__device__ float g_ctx[Mrows * Cdim];
__device__ float g_tmp[Mrows * Cdim];
__device__ float g_x1[Mrows * Cdim];
__device__ float g_h[Mrows * MLPD];
__device__ float g_ffn[Mrows * Cdim];
// split-fp16 planes of qdq(h) + fp16 fc2 weights (exact)
__device__ __half g_hhi[Mrows * MLPD];
__device__ __half g_hlo[Mrows * MLPD];
__device__ __half g_f2h[Cdim * MLPD];

// ---------------------------------------------------------------------------
// Packed f32x2 helpers (B300 dual-lane fp32 FMA)
// ---------------------------------------------------------------------------
typedef unsigned long long u64t;
__device__ __forceinline__ u64t pk2(float lo, float hi) {
    u64t d;
    asm("mov.b64 %0, {%1,%2};" : "=l"(d) : "f"(lo), "f"(hi));
    return d;
}
__device__ __forceinline__ void upk2(float& lo, float& hi, u64t d) {
    asm("mov.b64 {%0,%1}, %2;" : "=f"(lo), "=f"(hi) : "l"(d));
}
__device__ __forceinline__ void fma2(u64t& c, u64t a, u64t b) {
    asm("fma.rn.f32x2 %0, %1, %2, %0;" : "+l"(c) : "l"(a), "l"(b));
}
// mma helpers (sm_80 baseline)
__device__ __forceinline__ uint32_t smem_u32(const void* p) {
    uint32_t a;
    asm("{ .reg .u64 t; cvta.to.shared.u64 t, %1; cvt.u32.u64 %0, t; }" : "=r"(a) : "l"(p));
    return a;
}
__device__ __forceinline__ void ldsm4(uint32_t& r0, uint32_t& r1, uint32_t& r2, uint32_t& r3,
                                      uint32_t addr) {
    asm volatile("ldmatrix.sync.aligned.m8n8.x4.shared.b16 {%0,%1,%2,%3}, [%4];"
                 : "=r"(r0), "=r"(r1), "=r"(r2), "=r"(r3) : "r"(addr));
}
__device__ __forceinline__ void mma16816(float* c, const uint32_t* a, uint32_t b0, uint32_t b1) {
    asm volatile("mma.sync.aligned.m16n8k16.row.col.f32.f16.f16.f32 "
                 "{%0,%1,%2,%3}, {%4,%5,%6,%7}, {%8,%9}, {%0,%1,%2,%3};"
                 : "+f"(c[0]), "+f"(c[1]), "+f"(c[2]), "+f"(c[3])
                 : "r"(a[0]), "r"(a[1]), "r"(a[2]), "r"(a[3]), "r"(b0), "r"(b1));
}
__device__ __forceinline__ void cp16(uint32_t s, const void* g) {
    asm volatile("cp.async.ca.shared.global [%0], [%1], 16;" :: "r"(s), "l"(g));
}

// ---------------------------------------------------------------------------
// fp32 quantize-dequantize (bit-identical to R1/R9)
// ---------------------------------------------------------------------------
__global__ void qdq_kernel(const float* __restrict__ in, float* __restrict__ out,
                           float fmax, int e4m3)
{
    int blk  = blockIdx.x * 8 + (threadIdx.x >> 5);
    int lane = threadIdx.x & 31;
    size_t base = (size_t)blk * 128 + (size_t)lane * 4;
    float4 v = *reinterpret_cast<const float4*>(in + base);
    float am = fmaxf(fmaxf(fabsf(v.x), fabsf(v.y)), fmaxf(fabsf(v.z), fabsf(v.w)));
    #pragma unroll
    for (int o = 16; o > 0; o >>= 1)
        am = fmaxf(am, __shfl_xor_sync(0xffffffffu, am, o));
    float s = fmaxf(am / fmax, 1e-12f);
    float r4[4]; float xin[4] = {v.x, v.y, v.z, v.w};
    #pragma unroll
    for (int i = 0; i < 4; i++) {
        float r = xin[i] / s;
        __nv_fp8_storage_t f8 = __nv_cvt_float_to_fp8(r, __NV_SATFINITE, e4m3 ? __NV_E4M3 : __NV_E5M2);
        __half_raw hr = __nv_cvt_fp8_to_halfraw(f8, e4m3 ? __NV_E4M3 : __NV_E5M2);
        r4[i] = __half2float(*reinterpret_cast<__half*>(&hr)) * s;
    }
    float4 o4 = {r4[0], r4[1], r4[2], r4[3]};
    *reinterpret_cast<float4*>(out + base) = o4;
}

// qdq for h (E4M3) -> split fp16 planes (same fp32 qdq values, then hi/lo split)
__global__ void qdq_split(const float* __restrict__ in,
                          __half* __restrict__ hip, __half* __restrict__ lop, float fmax)
{
    int blk  = blockIdx.x * 8 + (threadIdx.x >> 5);
    int lane = threadIdx.x & 31;
    size_t base = (size_t)blk * 128 + (size_t)lane * 4;
    float4 v = *reinterpret_cast<const float4*>(in + base);
    float am = fmaxf(fmaxf(fabsf(v.x), fabsf(v.y)), fmaxf(fabsf(v.z), fabsf(v.w)));
    #pragma unroll
    for (int o = 16; o > 0; o >>= 1)
        am = fmaxf(am, __shfl_xor_sync(0xffffffffu, am, o));
    float s = fmaxf(am / fmax, 1e-12f);
    float xin[4] = {v.x, v.y, v.z, v.w};
    __half hh[4], hl[4];
    #pragma unroll
    for (int i = 0; i < 4; i++) {
        float r = xin[i] / s;
        __nv_fp8_storage_t f8 = __nv_cvt_float_to_fp8(r, __NV_SATFINITE, __NV_E4M3);
        __half_raw hr = __nv_cvt_fp8_to_halfraw(f8, __NV_E4M3);
        float val = __half2float(*reinterpret_cast<__half*>(&hr)) * s;
        hh[i] = __float2half_rn(val);
        hl[i] = __float2half_rn(val - __half2float(hh[i]));
    }
    *reinterpret_cast<uint2*>(hip + base) = *reinterpret_cast<uint2*>(hh);
    *reinterpret_cast<uint2*>(lop + base) = *reinterpret_cast<uint2*>(hl);
}

// f32 -> fp16 (exact for fp8-valued weights)
__global__ void conv_f16(const float* __restrict__ in, __half* __restrict__ out, int n4)
{
    int i = blockIdx.x * blockDim.x + threadIdx.x;
    if (i >= n4) return;
    float4 v = reinterpret_cast<const float4*>(in)[i];
    __half b[4] = {__float2half_rn(v.x), __float2half_rn(v.y),
                   __float2half_rn(v.z), __float2half_rn(v.w)};
    reinterpret_cast<uint2*>(out)[i] = *reinterpret_cast<uint2*>(b);
}

// ---------------------------------------------------------------------------
// wgemm2: split-fp16 HMMA GEMM for fc2. C[m,n]=ws*Σk(hi+lo)[m,k]*W[n,k]+bias.
// 256 thr (8 warps: wm 0-3 x wn 0-1, warp tile 32x64), BK=32, cp.async
// double-buffered, padded 80B fp16 rows (no swizzle). Fragment/mma mapping
// identical to the R10-validated kernel.
// ---------------------------------------------------------------------------
#define PADH 40                               // halves per row (32 data + 8 pad)
#define PLN  (128 * PADH)                     // halves per plane   (5120)
#define BUFH (3 * PLN)                        // halves per buffer  (15360)
#define W2_SMEM (2 * BUFH * 2)                // bytes (61440)

__global__ void __launch_bounds__(256, 2)
wgemm2(const __half* __restrict__ Ahi, const __half* __restrict__ Alo,
       const __half* __restrict__ W, float* __restrict__ C,
       int K, int N, const float* __restrict__ wscale, const float* __restrict__ bias)
{
    extern __shared__ __half sm2[];
    uint32_t smb = smem_u32(sm2);
    int tid = threadIdx.x, lane = tid & 31, wid = tid >> 5;
    int wm = wid & 3, wn = wid >> 2;
    int m0 = blockIdx.y * 128, n0 = blockIdx.x * 128;

    // loader: thread t fills 16 halves (32B) per array; row=t>>1, half-sel=t&1
    int lrow = tid >> 1, lh = tid & 1;
    const __half* gH = Ahi + (size_t)(m0 + lrow) * K + lh * 16;
    const __half* gL = Alo + (size_t)(m0 + lrow) * K + lh * 16;
    const __half* gW = W   + (size_t)(n0 + lrow) * K + lh * 16;
    uint32_t sRow = smb + (uint32_t)(lrow * PADH + lh * 16) * 2;   // byte addr in buffer 0

    float acc[2][8][4];
    #pragma unroll
    for (int mt = 0; mt < 2; mt++)
        #pragma unroll
        for (int nt = 0; nt < 8; nt++)
            #pragma unroll
            for (int c = 0; c < 4; c++) acc[mt][nt][c] = 0.0f;

    // prologue: fill buffer 0 (k-slice 0)
    cp16(sRow,                gH);      cp16(sRow + 16,                gH + 8);
    cp16(sRow + PLN * 2,      gL);      cp16(sRow + PLN * 2 + 16,      gL + 8);
    cp16(sRow + 2 * PLN * 2,  gW);      cp16(sRow + 2 * PLN * 2 + 16,  gW + 8);
    asm volatile("cp.async.commit_group;" ::: "memory");

    int nkt = K >> 5;   // BK=32
    for (int kt = 0; kt < nkt; kt++) {
        int cur = kt & 1;
        bool pf = (kt + 1) < nkt;
        if (pf) {
            uint32_t dst = sRow + (cur ^ 1) * (uint32_t)(BUFH * 2);
            const __half* pH = gH + (size_t)(kt + 1) * 32;
            const __half* pL = gL + (size_t)(kt + 1) * 32;
            const __half* pW = gW + (size_t)(kt + 1) * 32;
            cp16(dst,               pH);  cp16(dst + 16,               pH + 8);
            cp16(dst + PLN * 2,     pL);  cp16(dst + PLN * 2 + 16,     pL + 8);
            cp16(dst + 2 * PLN * 2, pW);  cp16(dst + 2 * PLN * 2 + 16, pW + 8);
            asm volatile("cp.async.commit_group;" ::: "memory");
            asm volatile("cp.async.wait_group 1;" ::: "memory");
        } else {
            asm volatile("cp.async.wait_group 0;" ::: "memory");
        }
        __syncthreads();

        uint32_t hb = smb + cur * (uint32_t)(BUFH * 2);
        uint32_t lb = hb + PLN * 2;
        uint32_t bb = hb + 2 * PLN * 2;
        #pragma unroll
        for (int ks = 0; ks < 2; ks++) {
            int kbyte = ks * 32 + (lane >> 4) * 16;
            uint32_t ah[2][4], al[2][4], br[4][4];
            #pragma unroll
            for (int mt = 0; mt < 2; mt++) {
                int ro = (wm * 32 + mt * 16 + (lane & 15)) * (PADH * 2) + kbyte;
                ldsm4(ah[mt][0], ah[mt][1], ah[mt][2], ah[mt][3], hb + ro);
                ldsm4(al[mt][0], al[mt][1], al[mt][2], al[mt][3], lb + ro);
            }
            #pragma unroll
            for (int ng = 0; ng < 4; ng++) {
                int ro = (wn * 64 + ng * 16 + (lane & 15)) * (PADH * 2) + kbyte;
                ldsm4(br[ng][0], br[ng][1], br[ng][2], br[ng][3], bb + ro);
            }
            #pragma unroll
            for (int mt = 0; mt < 2; mt++)
                #pragma unroll
                for (int nt = 0; nt < 8; nt++) {
                    int ng = nt >> 1, hf = nt & 1;
                    mma16816(acc[mt][nt], ah[mt], br[ng][hf], br[ng][2 + hf]);
                    mma16816(acc[mt][nt], al[mt], br[ng][hf], br[ng][2 + hf]);
                }
        }
        __syncthreads();
    }

    #pragma unroll
    for (int mt = 0; mt < 2; mt++) {
        int row = m0 + wm * 32 + mt * 16 + (lane >> 2);
        #pragma unroll
        for (int nt = 0; nt < 8; nt++) {
            int col = n0 + wn * 64 + nt * 8 + (lane & 3) * 2;
            float ws = wscale ? wscale[col >> 7] : 1.0f;
            float v0 = acc[mt][nt][0] * ws, v1 = acc[mt][nt][1] * ws;
            float v2 = acc[mt][nt][2] * ws, v3 = acc[mt][nt][3] * ws;
            if (bias) { float b0 = bias[col], b1 = bias[col + 1]; v0 += b0; v1 += b1; v2 += b0; v3 += b1; }
            *reinterpret_cast<float2*>(C + (size_t)row * N + col)       = make_float2(v0, v1);
            *reinterpret_cast<float2*>(C + (size_t)(row + 8) * N + col) = make_float2(v2, v3);
        }
    }
}

// ---------------------------------------------------------------------------
// Double-buffered fp32 SGEMM NT (verbatim R16 winner)
// ---------------------------------------------------------------------------
__global__ void __launch_bounds__(128, 2)
gemm_nt(const float* __restrict__ A, const float* __restrict__ W, float* __restrict__ C,
        int K, int lda, int ldb, int ldc,
        int zdiv, long long sA1, long long sA2, long long sB1, long long sB2,
        long long sC1, long long sC2,
        const float* __restrict__ wscale, const float* __restrict__ bias,
        int act, int causal)
{
    __shared__ float As[2][8][132];
    __shared__ float Bs[2][8][132];
    int z = blockIdx.z;
    int z1 = z / zdiv, z2 = z % zdiv;
    A += z1 * sA1 + z2 * sA2;
    W += z1 * sB1 + z2 * sB2;
    C += z1 * sC1 + z2 * sC2;

    int m0 = blockIdx.y * 128, n0 = blockIdx.x * 128;
    if (causal && n0 > m0 + 127) return;

    int tid = threadIdx.x;
    int tx = tid & 15, ty = tid >> 4;
    const float* gA = A + (size_t)(m0 + tid) * lda;
    const float* gB = W + (size_t)(n0 + tid) * ldb;

    u64t acc2[8][8];
    #pragma unroll
    for (int p = 0; p < 8; p++)
        #pragma unroll
        for (int j = 0; j < 8; j++) acc2[p][j] = 0ull;

    float4 av0 = *reinterpret_cast<const float4*>(gA);
    float4 av1 = *reinterpret_cast<const float4*>(gA + 4);
    float4 bv0 = *reinterpret_cast<const float4*>(gB);
    float4 bv1 = *reinterpret_cast<const float4*>(gB + 4);
    {
        float a8[8] = {av0.x, av0.y, av0.z, av0.w, av1.x, av1.y, av1.z, av1.w};
        float b8[8] = {bv0.x, bv0.y, bv0.z, bv0.w, bv1.x, bv1.y, bv1.z, bv1.w};
        #pragma unroll
        for (int q = 0; q < 8; q++) { As[0][q][tid] = a8[q]; Bs[0][q][tid] = b8[q]; }
    }
    __syncthreads();

    int nkt = K >> 3;
    for (int kt = 0; kt < nkt; kt++) {
        int cur = kt & 1;
        bool pf = (kt + 1) < nkt;
        if (pf) {
            const float* pA = gA + (kt + 1) * 8;
            const float* pB = gB + (kt + 1) * 8;
            av0 = *reinterpret_cast<const float4*>(pA);
            av1 = *reinterpret_cast<const float4*>(pA + 4);
            bv0 = *reinterpret_cast<const float4*>(pB);
            bv1 = *reinterpret_cast<const float4*>(pB + 4);
        }
        #pragma unroll
        for (int kk = 0; kk < 8; kk++) {
            float4 a0 = *reinterpret_cast<const float4*>(&As[cur][kk][ty * 16]);
            float4 a1 = *reinterpret_cast<const float4*>(&As[cur][kk][ty * 16 + 4]);
            float4 a2 = *reinterpret_cast<const float4*>(&As[cur][kk][ty * 16 + 8]);
            float4 a3 = *reinterpret_cast<const float4*>(&As[cur][kk][ty * 16 + 12]);
            float4 b0 = *reinterpret_cast<const float4*>(&Bs[cur][kk][tx * 4]);
            float4 b1 = *reinterpret_cast<const float4*>(&Bs[cur][kk][64 + tx * 4]);
            u64t ad[8];
            ad[0] = pk2(a0.x, a0.y); ad[1] = pk2(a0.z, a0.w);
            ad[2] = pk2(a1.x, a1.y); ad[3] = pk2(a1.z, a1.w);
            ad[4] = pk2(a2.x, a2.y); ad[5] = pk2(a2.z, a2.w);
            ad[6] = pk2(a3.x, a3.y); ad[7] = pk2(a3.z, a3.w);
            u64t bd[8];
            bd[0] = pk2(b0.x, b0.x); bd[1] = pk2(b0.y, b0.y);
            bd[2] = pk2(b0.z, b0.z); bd[3] = pk2(b0.w, b0.w);
            bd[4] = pk2(b1.x, b1.x); bd[5] = pk2(b1.y, b1.y);
            bd[6] = pk2(b1.z, b1.z); bd[7] = pk2(b1.w, b1.w);
            #pragma unroll
            for (int p = 0; p < 8; p++)
                #pragma unroll
                for (int j = 0; j < 8; j++) fma2(acc2[p][j], ad[p], bd[j]);
        }
        if (pf) {
            int nb = cur ^ 1;
            float a8[8] = {av0.x, av0.y, av0.z, av0.w, av1.x, av1.y, av1.z, av1.w};
            float b8[8] = {bv0.x, bv0.y, bv0.z, bv0.w, bv1.x, bv1.y, bv1.z, bv1.w};
            #pragma unroll
            for (int q = 0; q < 8; q++) { As[nb][q][tid] = a8[q]; Bs[nb][q][tid] = b8[q]; }
        }
        __syncthreads();
    }

    #pragma unroll
    for (int p = 0; p < 8; p++) {
        #pragma unroll
        for (int g = 0; g < 2; g++) {
            int ncol = n0 + g * 64 + tx * 4;
            float ws = wscale ? wscale[ncol >> 7] : 1.0f;
            float r0[4], r1[4];
            #pragma unroll
            for (int c = 0; c < 4; c++) {
                float vlo, vhi;
                upk2(vlo, vhi, acc2[p][g * 4 + c]);
                vlo *= ws; vhi *= ws;
                if (bias) { float bb = bias[ncol + c]; vlo += bb; vhi += bb; }
                if (act) {
                    vlo = 0.5f * vlo * (1.0f + erff(vlo * 0.7071067811865476f));
                    vhi = 0.5f * vhi * (1.0f + erff(vhi * 0.7071067811865476f));
                }
                r0[c] = vlo; r1[c] = vhi;
            }
            int m = m0 + ty * 16 + p * 2;
            *reinterpret_cast<float4*>(C + (size_t)m * ldc + ncol)       = *reinterpret_cast<float4*>(r0);
            *reinterpret_cast<float4*>(C + (size_t)(m + 1) * ldc + ncol) = *reinterpret_cast<float4*>(r1);
        }
    }
}

// ---------------------------------------------------------------------------
// Double-buffered fp32 SGEMM NN (verbatim R16 winner; causal K cap)
// ---------------------------------------------------------------------------
__global__ void __launch_bounds__(256, 2)
gemm_nn(const float* __restrict__ A, const float* __restrict__ Bm, float* __restrict__ C,
        int K, int lda, int ldb, int ldc,
        int zdiv, long long sA1, long long sA2, long long sB1, long long sB2,
        long long sC1, long long sC2, int causal)
{
    __shared__ float As[2][8][132];
    __shared__ float Bs[2][8][132];
    int z = blockIdx.z;
    int z1 = z / zdiv, z2 = z % zdiv;
    A  += z1 * sA1 + z2 * sA2;
    Bm += z1 * sB1 + z2 * sB2;
    C  += z1 * sC1 + z2 * sC2;
    int tid = threadIdx.x;
    int tx = tid & 15, ty = tid >> 4;
    int m0 = blockIdx.y * 128, n0 = blockIdx.x * 128;
    int arow = tid >> 1, acol = (tid & 1) * 4;
    int brow = tid >> 5, bcol = (tid & 31) * 4;
    const float* gA = A + (size_t)(m0 + arow) * lda + acol;
    const float* gB = Bm + (size_t)brow * ldb + n0 + bcol;

    int Keff = causal ? (m0 + 128 < K ? m0 + 128 : K) : K;

    u64t acc2[4][8];
    #pragma unroll
    for (int p = 0; p < 4; p++)
        #pragma unroll
        for (int j = 0; j < 8; j++) acc2[p][j] = 0ull;

    float4 av = *reinterpret_cast<const float4*>(gA);
    float4 bv = *reinterpret_cast<const float4*>(gB);
    As[0][acol + 0][arow] = av.x; As[0][acol + 1][arow] = av.y;
    As[0][acol + 2][arow] = av.z; As[0][acol + 3][arow] = av.w;
    *reinterpret_cast<float4*>(&Bs[0][brow][bcol]) = bv;
    __syncthreads();

    int nkt = Keff >> 3;
    for (int kt = 0; kt < nkt; kt++) {
        int cur = kt & 1;
        bool pf = (kt + 1) < nkt;
        if (pf) {
            av = *reinterpret_cast<const float4*>(gA + (kt + 1) * 8);
            bv = *reinterpret_cast<const float4*>(gB + (size_t)(kt + 1) * 8 * ldb);
        }
        #pragma unroll
        for (int kk = 0; kk < 8; kk++) {
            float4 a0 = *reinterpret_cast<const float4*>(&As[cur][kk][ty * 8]);
            float4 a1 = *reinterpret_cast<const float4*>(&As[cur][kk][ty * 8 + 4]);
            float4 b0 = *reinterpret_cast<const float4*>(&Bs[cur][kk][tx * 4]);
            float4 b1 = *reinterpret_cast<const float4*>(&Bs[cur][kk][64 + tx * 4]);
            u64t ad[4];
            ad[0] = pk2(a0.x, a0.y); ad[1] = pk2(a0.z, a0.w);
            ad[2] = pk2(a1.x, a1.y); ad[3] = pk2(a1.z, a1.w);
            u64t bd[8];
            bd[0] = pk2(b0.x, b0.x); bd[1] = pk2(b0.y, b0.y);
            bd[2] = pk2(b0.z, b0.z); bd[3] = pk2(b0.w, b0.w);
            bd[4] = pk2(b1.x, b1.x); bd[5] = pk2(b1.y, b1.y);
            bd[6] = pk2(b1.z, b1.z); bd[7] = pk2(b1.w, b1.w);
            #pragma unroll
            for (int p = 0; p < 4; p++)
                #pragma unroll
                for (int j = 0; j < 8; j++) fma2(acc2[p][j], ad[p], bd[j]);
        }
        if (pf) {
            int nb = cur ^ 1;
            As[nb][acol + 0][arow] = av.x; As[nb][acol + 1][arow] = av.y;
            As[nb][acol + 2][arow] = av.z; As[nb][acol + 3][arow] = av.w;
            *reinterpret_cast<float4*>(&Bs[nb][brow][bcol]) = bv;
        }
        __syncthreads();
    }

    #pragma unroll
    for (int p = 0; p < 4; p++) {
        #pragma unroll
        for (int g = 0; g < 2; g++) {
            int ncol = n0 + g * 64 + tx * 4;
            float r0[4], r1[4];
            #pragma unroll
            for (int c = 0; c < 4; c++) {
                float vlo, vhi;
                upk2(vlo, vhi, acc2[p][g * 4 + c]);
                r0[c] = vlo; r1[c] = vhi;
            }
            int m = m0 + ty * 8 + p * 2;
            *reinterpret_cast<float4*>(C + (size_t)m * ldc + ncol)       = *reinterpret_cast<float4*>(r0);
            *reinterpret_cast<float4*>(C + (size_t)(m + 1) * ldc + ncol) = *reinterpret_cast<float4*>(r1);
        }
    }
}

// ---------------------------------------------------------------------------
// Causal-masked softmax — verbatim R1/R9
// ---------------------------------------------------------------------------
__global__ void softmax_kernel(float* __restrict__ S, const int* __restrict__ mask, float scale)
{
    int row = blockIdx.x;
    int q = row % Tt;
    int b = row / (Hh * Tt);
    float* sr = S + (size_t)row * Tt;
    const int* mr = mask + ((size_t)b * Tt + q) * Tt;
    int tid = threadIdx.x;
    __shared__ float red[256];
    float vals[4];
    float lmax = -INFINITY;
    #pragma unroll
    for (int it = 0; it < 4; it++) {
        int i = tid + it * 256;
        float v = mr[i] ? sr[i] * scale : -INFINITY;
        vals[it] = v;
        lmax = fmaxf(lmax, v);
    }
    red[tid] = lmax; __syncthreads();
    for (int o = 128; o > 0; o >>= 1) {
        if (tid < o) red[tid] = fmaxf(red[tid], red[tid + o]);
        __syncthreads();
    }
    float mx = red[0];
    __syncthreads();
    float lsum = 0.0f;
    #pragma unroll
    for (int it = 0; it < 4; it++) {
        float e = expf(vals[it] - mx);
        vals[it] = e;
        lsum += e;
    }
    red[tid] = lsum; __syncthreads();
    for (int o = 128; o > 0; o >>= 1) {
        if (tid < o) red[tid] += red[tid + o];
        __syncthreads();
    }
    float inv = 1.0f / red[0];
    #pragma unroll
    for (int it = 0; it < 4; it++) {
        int i = tid + it * 256;
        sr[i] = vals[it] * inv;
    }
}

// ---------------------------------------------------------------------------
// LayerNorm(x + y) — verbatim R1/R9
// ---------------------------------------------------------------------------
__global__ void addln_kernel(const float* __restrict__ x, const float* __restrict__ y,
                             float* __restrict__ out,
                             const float* __restrict__ g, const float* __restrict__ gs,
                             const float* __restrict__ b, const float* __restrict__ bs)
{
    int row = blockIdx.x;
    const float* xr = x + (size_t)row * Cdim;
    const float* yr = y + (size_t)row * Cdim;
    float* outr = out + (size_t)row * Cdim;
    __shared__ float buf[Cdim];
    __shared__ float red[256];
    int tid = threadIdx.x;
    float lsum = 0.0f;
    #pragma unroll
    for (int it = 0; it < Cdim / 256; it++) {
        int i = tid + it * 256;
        float v = xr[i] + yr[i];
        buf[i] = v;
        lsum += v;
    }
    red[tid] = lsum; __syncthreads();
    for (int o = 128; o > 0; o >>= 1) {
        if (tid < o) red[tid] += red[tid + o];
        __syncthreads();
    }
    float mean = red[0] * (1.0f / Cdim);
    __syncthreads();
    float lvar = 0.0f;
    #pragma unroll
    for (int it = 0; it < Cdim / 256; it++) {
        int i = tid + it * 256;
        float d = buf[i] - mean;
        lvar += d * d;
    }
    red[tid] = lvar; __syncthreads();
    for (int o = 128; o > 0; o >>= 1) {
        if (tid < o) red[tid] += red[tid + o];
        __syncthreads();
    }
    float rstd = rsqrtf(red[0] * (1.0f / Cdim) + 1e-5f);
    #pragma unroll
    for (int it = 0; it < Cdim / 256; it++) {
        int i = tid + it * 256;
        float d = (buf[i] - mean) * rstd;
        outr[i] = d * (g[i] * gs[i >> 7]) + b[i] * bs[i >> 7];
    }
}

// ---------------------------------------------------------------------------
// Launch pipeline
// ---------------------------------------------------------------------------
extern "C" void kernel_launch(void* const* d_in, const int* in_sizes, int n_in,
                              void* d_out, int out_size)
{
    const float* x     = (const float*)d_in[0];
    const int*   mask  = (const int*)  d_in[1];
    const float* wq    = (const float*)d_in[2];
    const float* qs    = (const float*)d_in[3];
    const float* wk    = (const float*)d_in[4];
    const float* ks    = (const float*)d_in[5];
    const float* wv    = (const float*)d_in[6];
    const float* vs    = (const float*)d_in[7];
    const float* wo    = (const float*)d_in[8];
    const float* os_   = (const float*)d_in[9];
    const float* fc1w  = (const float*)d_in[10];
    const float* fc1s  = (const float*)d_in[11];
    const float* fc1b  = (const float*)d_in[12];
    const float* fc2w  = (const float*)d_in[13];
    const float* fc2s  = (const float*)d_in[14];
    const float* fc2b  = (const float*)d_in[15];
    const float* l1g   = (const float*)d_in[16];
    const float* l1gs  = (const float*)d_in[17];
    const float* l1b   = (const float*)d_in[18];
    const float* l1bs  = (const float*)d_in[19];
    const float* l2g   = (const float*)d_in[20];
    const float* l2gs  = (const float*)d_in[21];
    const float* l2b   = (const float*)d_in[22];
    const float* l2bs  = (const float*)d_in[23];
    float* out = (float*)d_out;

    void* p;
    cudaGetSymbolAddress(&p, g_xdq);    float* xdq = (float*)p;
    cudaGetSymbolAddress(&p, g_q);      float* qb  = (float*)p;
    cudaGetSymbolAddress(&p, g_k);      float* kb  = (float*)p;
    cudaGetSymbolAddress(&p, g_v);      float* vb  = (float*)p;
    cudaGetSymbolAddress(&p, g_scores); float* sc  = (float*)p;
    cudaGetSymbolAddress(&p, g_ctx);    float* ctx = (float*)p;
    cudaGetSymbolAddress(&p, g_tmp);    float* tmp = (float*)p;
    cudaGetSymbolAddress(&p, g_x1);     float* x1  = (float*)p;
    cudaGetSymbolAddress(&p, g_h);      float* hb  = (float*)p;
    cudaGetSymbolAddress(&p, g_ffn);    float* ffn = (float*)p;
    cudaGetSymbolAddress(&p, g_hhi);    __half* hhi = (__half*)p;
    cudaGetSymbolAddress(&p, g_hlo);    __half* hlo = (__half*)p;
    cudaGetSymbolAddress(&p, g_f2h);    __half* f2h = (__half*)p;

    cudaFuncSetAttribute(wgemm2, cudaFuncAttributeMaxDynamicSharedMemorySize, W2_SMEM);

    const float E5MAX = 57344.0f, E4MAX = 448.0f;
    const float INV_SQRT_HD = 0.08838834764831845f;

    // fc2 weight -> fp16 (exact)
    int nmc = MLPD * Cdim / 4;
    conv_f16<<<(nmc + 255) / 256, 256>>>(fc2w, f2h, nmc);

    // 1. qdq x (E5M2)
    qdq_kernel<<<(Mrows * Cdim / 128) / 8, 256>>>(x, xdq, E5MAX, 0);

    // 2. QKV projections (fp32 f32x2)
    dim3 gl(Cdim / 128, Mrows / 128, 1);
    gemm_nt<<<gl, 128>>>(xdq, wq, qb, Cdim, Cdim, Cdim, Cdim,
                         1, 0, 0, 0, 0, 0, 0, qs, nullptr, 0, 0);
    gemm_nt<<<gl, 128>>>(xdq, wk, kb, Cdim, Cdim, Cdim, Cdim,
                         1, 0, 0, 0, 0, 0, 0, ks, nullptr, 0, 0);
    gemm_nt<<<gl, 128>>>(xdq, wv, vb, Cdim, Cdim, Cdim, Cdim,
                         1, 0, 0, 0, 0, 0, 0, vs, nullptr, 0, 0);

    // 3. scores = Q @ K^T (causal tiles only)
    dim3 gsc(Tt / 128, Tt / 128, Bb * Hh);
    gemm_nt<<<gsc, 128>>>(qb, kb, sc, HDim, Cdim, Cdim, Tt,
                          Hh, (long long)Tt * Cdim, 128, (long long)Tt * Cdim, 128,
                          (long long)Hh * Tt * Tt, (long long)Tt * Tt,
                          nullptr, nullptr, 0, 1);

    // 4. masked softmax
    softmax_kernel<<<Bb * Hh * Tt, 256>>>(sc, mask, INV_SQRT_HD);

    // 5. ctx = attn @ V (K capped causally)
    dim3 gcx(1, Tt / 128, Bb * Hh);
    gemm_nn<<<gcx, 256>>>(sc, vb, ctx, Tt, Tt, Cdim, Cdim,
                          Hh, (long long)Hh * Tt * Tt, (long long)Tt * Tt,
                          (long long)Tt * Cdim, 128, (long long)Tt * Cdim, 128, 1);

    // 6. out projection
    qdq_kernel<<<(Mrows * Cdim / 128) / 8, 256>>>(ctx, xdq, E5MAX, 0);
    gemm_nt<<<gl, 128>>>(xdq, wo, tmp, Cdim, Cdim, Cdim, Cdim,
                         1, 0, 0, 0, 0, 0, 0, os_, nullptr, 0, 0);

    // 7. x1 = LN1(x + attn_out)
    addln_kernel<<<Mrows, 256>>>(x, tmp, x1, l1g, l1gs, l1b, l1bs);

    // 8. fc1 + bias + exact GELU (fp32)
    qdq_kernel<<<(Mrows * Cdim / 128) / 8, 256>>>(x1, xdq, E4MAX, 1);
    dim3 gf1(MLPD / 128, Mrows / 128, 1);
    gemm_nt<<<gf1, 128>>>(xdq, fc1w, hb, Cdim, Cdim, Cdim, MLPD,
                          1, 0, 0, 0, 0, 0, 0, fc1s, fc1b, 1, 0);

    // 9. fc2 via split-fp16 HMMA (flip-safe: no qdq downstream)
    qdq_split<<<(Mrows * MLPD / 128) / 8, 256>>>(hb, hhi, hlo, E4MAX);
    dim3 gf2(Cdim / 128, Mrows / 128, 1);
    wgemm2<<<gf2, 256, W2_SMEM>>>(hhi, hlo, f2h, ffn, MLPD, Cdim, fc2s, fc2b);

    // 10. out = LN2(x1 + ffn)
    addln_kernel<<<Mrows, 256>>>(x1, ffn, out, l2g, l2gs, l2b, l2bs);
}